// round 5
// baseline (speedup 1.0000x reference)
#include <cuda_runtime.h>
#include <stdint.h>
#include <math.h>

#define Bimg 16
#define Nbox 16
#define Him  640
#define Wim  640
#define PHp  300
#define PWp  300
#define PTOT (PHp*PWp*3)

// ---------------------------------------------------------------------------
// JAX threefry2x32 (20 rounds), partitionable random-bits convention
// ---------------------------------------------------------------------------
__device__ __forceinline__ void tf2x32(uint32_t k0, uint32_t k1,
                                       uint32_t x0, uint32_t x1,
                                       uint32_t& o0, uint32_t& o1) {
    uint32_t ks2 = k0 ^ k1 ^ 0x1BD11BDAu;
    x0 += k0; x1 += k1;
#define TF_RND(r) { x0 += x1; x1 = __funnelshift_l(x1, x1, (r)); x1 ^= x0; }
    TF_RND(13) TF_RND(15) TF_RND(26) TF_RND(6)
    x0 += k1;  x1 += ks2 + 1u;
    TF_RND(17) TF_RND(29) TF_RND(16) TF_RND(24)
    x0 += ks2; x1 += k0 + 2u;
    TF_RND(13) TF_RND(15) TF_RND(26) TF_RND(6)
    x0 += k0;  x1 += k1 + 3u;
    TF_RND(17) TF_RND(29) TF_RND(16) TF_RND(24)
    x0 += k1;  x1 += ks2 + 4u;
    TF_RND(13) TF_RND(15) TF_RND(26) TF_RND(6)
    x0 += ks2; x1 += k0 + 5u;
#undef TF_RND
    o0 = x0; o1 = x1;
}

__device__ __forceinline__ uint32_t rbits(uint32_t k0, uint32_t k1, uint64_t idx) {
    uint32_t a, b;
    tf2x32(k0, k1, (uint32_t)(idx >> 32), (uint32_t)idx, a, b);
    return a ^ b;
}

// 3 interleaved threefry chains, counters (c0, c0+1, c0+2), hi word = 0.
__device__ __forceinline__ void tf3(uint32_t k0, uint32_t k1, uint32_t c0,
                                    uint32_t out[3]) {
    uint32_t ks2 = k0 ^ k1 ^ 0x1BD11BDAu;
    uint32_t a0 = k0, a1 = k0, a2 = k0;
    uint32_t b0 = c0 + k1, b1 = c0 + 1u + k1, b2 = c0 + 2u + k1;
#define R3(r)  { a0 += b0; b0 = __funnelshift_l(b0,b0,(r)); b0 ^= a0; \
                 a1 += b1; b1 = __funnelshift_l(b1,b1,(r)); b1 ^= a1; \
                 a2 += b2; b2 = __funnelshift_l(b2,b2,(r)); b2 ^= a2; }
#define INJ3(ka, kb) { a0 += (ka); b0 += (kb); a1 += (ka); b1 += (kb); a2 += (ka); b2 += (kb); }
    R3(13) R3(15) R3(26) R3(6)
    INJ3(k1, ks2 + 1u)
    R3(17) R3(29) R3(16) R3(24)
    INJ3(ks2, k0 + 2u)
    R3(13) R3(15) R3(26) R3(6)
    INJ3(k0, k1 + 3u)
    R3(17) R3(29) R3(16) R3(24)
    INJ3(k1, ks2 + 4u)
    R3(13) R3(15) R3(26) R3(6)
    out[0] = (a0 + ks2) ^ (b0 + k0 + 5u);
    out[1] = (a1 + ks2) ^ (b1 + k0 + 5u);
    out[2] = (a2 + ks2) ^ (b2 + k0 + 5u);
#undef R3
#undef INJ3
}

__device__ __forceinline__ float bits_to_unit(uint32_t bits) {
    return __uint_as_float((bits >> 9) | 0x3f800000u) - 1.0f;
}

__device__ __forceinline__ float juniform(uint32_t k0, uint32_t k1, uint64_t i,
                                          float lo, float hi) {
    float f = bits_to_unit(rbits(k0, k1, i));
    return fmaxf(lo, f * (hi - lo) + lo);
}

__device__ __forceinline__ float erfinv_xla(float x) {
    float w = -log1pf(-x * x);
    float p;
    if (w < 5.0f) {
        w -= 2.5f;
        p = 2.81022636e-08f;
        p = fmaf(p, w, 3.43273939e-07f);
        p = fmaf(p, w, -3.5233877e-06f);
        p = fmaf(p, w, -4.39150654e-06f);
        p = fmaf(p, w, 0.00021858087f);
        p = fmaf(p, w, -0.00125372503f);
        p = fmaf(p, w, -0.00417768164f);
        p = fmaf(p, w, 0.246640727f);
        p = fmaf(p, w, 1.50140941f);
    } else {
        w = sqrtf(w) - 3.0f;
        p = -0.000200214257f;
        p = fmaf(p, w, 0.000100950558f);
        p = fmaf(p, w, 0.00134934322f);
        p = fmaf(p, w, -0.00367342844f);
        p = fmaf(p, w, 0.00573950773f);
        p = fmaf(p, w, -0.0076224613f);
        p = fmaf(p, w, 0.00943887047f);
        p = fmaf(p, w, 1.00167406f);
        p = fmaf(p, w, 2.83297682f);
    }
    return p * x;
}

__device__ __forceinline__ float jnormal(uint32_t k0, uint32_t k1, uint64_t i) {
    const float lo = -0.99999994f;
    float u = juniform(k0, k1, i, lo, 1.0f);
    return 1.41421354f * erfinv_xla(u);
}

// w,b jitter scalars for image b (deterministic key chain)
__device__ __forceinline__ void wb_for(int b, float w[3], float bb[3]) {
    uint32_t ib0, ib1;
    tf2x32(0u, 42u, 0u, (uint32_t)b, ib0, ib1);
    uint32_t kw0, kw1, kB0, kB1;
    tf2x32(ib0, ib1, 0u, 0u, kw0, kw1);
    tf2x32(ib0, ib1, 0u, 1u, kB0, kB1);
    #pragma unroll
    for (int c = 0; c < 3; c++) {
        w[c]  = jnormal(kw0, kw1, (uint64_t)c) * 0.1f + 0.5f;
        bb[c] = jnormal(kB0, kB1, (uint64_t)c) * 0.01f;
    }
}

// ---------------------------------------------------------------------------
// Device scratch
// ---------------------------------------------------------------------------
struct Geo {
    float y0i, x0i, diagi, phi, cc, top, r, ca, sa, bright;
    uint32_t k2a, k2b;
    int valid;
    int pad;
};                                      // 14 words = 56 B

#define NIMG_CHUNK 64
#define NPAT_CHUNK 8

__device__ Geo   g_geo[Bimg][Nbox];
__device__ float g_w[Bimg][3];
__device__ float g_bj[Bimg][3];
__device__ float g_isum[Bimg][NIMG_CHUNK];
__device__ float g_psum[Bimg][NPAT_CHUNK];

// ---------------------------------------------------------------------------
// K1: fused setup + sums (f32 accumulation). grid (73, 16), 256 thr.
//   x <  64 : image partial sums
//   x 64..71: clipped-patch partial sums (w,b computed inline)
//   x == 72 : per-box geometry + g_w/g_bj
// ---------------------------------------------------------------------------
__global__ void k_sums(const float* __restrict__ images,
                       const float* __restrict__ patch,
                       const float* __restrict__ boxes,
                       const float* __restrict__ scale_p) {
    int b = blockIdx.y, g = blockIdx.x;

    if (g == NIMG_CHUNK + NPAT_CHUNK) {
        int n = threadIdx.x;
        if (n == 0) {
            float w[3], bb[3];
            wb_for(b, w, bb);
            #pragma unroll
            for (int c = 0; c < 3; c++) { g_w[b][c] = w[c]; g_bj[b][c] = bb[c]; }
        }
        if (n < Nbox) {
            float scale = scale_p[0];
            uint32_t ib0, ib1, kl0, kl1;
            tf2x32(0u, 42u, 0u, (uint32_t)b, ib0, ib1);
            tf2x32(ib0, ib1, 0u, 2u, kl0, kl1);
            uint32_t kn0, kn1;
            tf2x32(kl0, kl1, 0u, (uint32_t)n, kn0, kn1);
            uint32_t k10, k11, k20, k21, k30, k31;
            tf2x32(kn0, kn1, 0u, 0u, k10, k11);
            tf2x32(kn0, kn1, 0u, 1u, k20, k21);
            tf2x32(kn0, kn1, 0u, 2u, k30, k31);

            const float MAXA = (float)(20.0 * 3.14159265358979323846 / 180.0);
            float angle  = juniform(k10, k11, 0ull, -MAXA, MAXA);
            float bright = juniform(k30, k31, 0ull, -0.3f, 0.3f);

            const float* bx = boxes + ((size_t)b * Nbox + n) * 4;
            float ymin = bx[0], xmin = bx[1], ymax = bx[2], xmax = bx[3];
            float h  = ymax - ymin;
            float ww = xmax - xmin;
            float longer = fmaxf(h, ww);
            float ps   = floorf(longer * scale);
            float diag = fminf(sqrtf(2.0f) * ps, (float)Wim);
            float oy = ymin + h * 0.5f;
            float ox = xmin + ww * 0.5f;
            float y0 = fmaxf(oy - diag * 0.5f, 0.0f);
            float x0 = fmaxf(ox - diag * 0.5f, 0.0f);
            y0 = (y0 + diag > (float)Him) ? ((float)Him - diag) : y0;
            x0 = (x0 + diag > (float)Wim) ? ((float)Wim - diag) : x0;
            float phi   = fmaxf(floorf(ps), 1.0f);
            float diagi = floorf(diag);

            Geo gg;
            gg.y0i = floorf(y0); gg.x0i = floorf(x0);
            gg.diagi = diagi; gg.phi = phi;
            gg.cc  = (diagi - 1.0f) * 0.5f;
            gg.top = floorf((diagi - phi) * 0.5f);
            gg.r   = 300.0f / phi;
            gg.ca  = cosf(angle);
            gg.sa  = sinf(angle);
            gg.bright = bright;
            gg.k2a = k20; gg.k2b = k21;
            gg.valid = (phi * phi > 60.0f) ? 1 : 0;
            gg.pad = 0;
            g_geo[b][n] = gg;
        }
        return;
    }

    float acc = 0.0f;
    if (g < NIMG_CHUNK) {
        const size_t IMG = (size_t)Him * Wim * 3;
        size_t base = (size_t)b * IMG + (size_t)g * (IMG / NIMG_CHUNK);
        const float4* src = (const float4*)(images + base);
        const int nvec = (int)((IMG / NIMG_CHUNK) / 4);   // 4800 float4s
        float a0 = 0.f, a1 = 0.f, a2 = 0.f, a3 = 0.f;
        float a4 = 0.f, a5 = 0.f, a6 = 0.f, a7 = 0.f;
        int i = threadIdx.x;
        for (; i + 256 < nvec; i += 512) {
            float4 v = src[i];
            float4 u = src[i + 256];
            a0 += v.x; a1 += v.y; a2 += v.z; a3 += v.w;
            a4 += u.x; a5 += u.y; a6 += u.z; a7 += u.w;
        }
        if (i < nvec) {
            float4 v = src[i];
            a0 += v.x; a1 += v.y; a2 += v.z; a3 += v.w;
        }
        acc = ((a0 + a1) + (a2 + a3)) + ((a4 + a5) + (a6 + a7));
    } else {
        float w[3], bb[3];
        wb_for(b, w, bb);
        int gp = g - NIMG_CHUNK;
        int chunk = PTOT / NPAT_CHUNK;                    // 33750
        int base = gp * chunk;
        float a0 = 0.f, a1 = 0.f;
        int i = base + threadIdx.x;
        int end = base + chunk;
        for (; i + 256 < end; i += 512) {
            int c0 = i % 3;
            int c1 = (i + 256) % 3;
            a0 += fminf(fmaxf(w[c0] * patch[i] + bb[c0], -1.0f), 1.0f);
            a1 += fminf(fmaxf(w[c1] * patch[i + 256] + bb[c1], -1.0f), 1.0f);
        }
        if (i < end) {
            int c = i % 3;
            a0 += fminf(fmaxf(w[c] * patch[i] + bb[c], -1.0f), 1.0f);
        }
        acc = a0 + a1;
    }
    __shared__ float sh[256];
    sh[threadIdx.x] = acc;
    __syncthreads();
    for (int s = 128; s > 0; s >>= 1) {
        if (threadIdx.x < s) sh[threadIdx.x] += sh[threadIdx.x + s];
        __syncthreads();
    }
    if (threadIdx.x == 0) {
        if (g < NIMG_CHUNK) g_isum[b][g] = sh[0];
        else                g_psum[b][g - NIMG_CHUNK] = sh[0];
    }
}

// ---------------------------------------------------------------------------
// K2: main paste kernel. grid (20, 80, 16), block (32, 8) = 32x8 px tiles.
// Smem-staged float4 I/O; on-the-fly patch adjust; compacted heavy phase.
// ---------------------------------------------------------------------------
__global__ void k_main(const float* __restrict__ images,
                       const float* __restrict__ patch,
                       float* __restrict__ oimg,
                       float* __restrict__ omask) {
    __shared__ Geo   sg[Nbox];
    __shared__ float simg[8 * 96];      // tile pixels, row-major, 3 ch
    __shared__ float smsk[8 * 96];
    __shared__ float spy[256], spx[256];
    __shared__ int   spk[256];
    __shared__ int   scnt;
    __shared__ float s_s;

    int b = blockIdx.z;
    int t = threadIdx.y * 32 + threadIdx.x;
    if (t < Nbox * 14)
        ((float*)sg)[t] = ((const float*)&g_geo[b][0])[t];
    if (t == 0) scnt = 0;
    __syncthreads();

    int x0t = blockIdx.x * 32;
    int y0t = blockIdx.y * 8;
    float tx0 = (float)x0t;
    float ty0 = (float)y0t;

    unsigned m = 0;
    #pragma unroll
    for (int n = 0; n < Nbox; n++) {
        const Geo& G = sg[n];
        bool ov = G.valid &&
                  (ty0 + 8.0f > G.y0i) && (ty0 < G.y0i + G.diagi) &&
                  (tx0 + 32.0f > G.x0i) && (tx0 < G.x0i + G.diagi);
        if (ov) m |= (1u << n);
    }

    // float4 row base (always float4-aligned: x0t%32==0 -> *3 %4==0)
    const float4 zero4 = make_float4(0.f, 0.f, 0.f, 0.f);

    if (m == 0) {
        // fast path: pure copy + zero, fully coalesced
        if (t < 192) {
            int r = t / 24, c = t % 24;
            size_t f4 = ((((size_t)(b * Him + y0t + r)) * Wim + x0t) * 3) >> 2;
            float4 v = ((const float4*)images)[f4 + c];
            ((float4*)oimg)[f4 + c]  = v;
            ((float4*)omask)[f4 + c] = zero4;
        }
        return;
    }

    // stage input tile + zero mask tile
    if (t < 192) {
        int r = t / 24, c = t % 24;
        size_t f4 = ((((size_t)(b * Him + y0t + r)) * Wim + x0t) * 3) >> 2;
        float4 v = ((const float4*)images)[f4 + c];
        ((float4*)simg)[r * 24 + c] = v;
        ((float4*)smsk)[r * 24 + c] = zero4;
    }
    if (t == 0) {
        // brightness shift s = mean(img) - mean(adjusted patch)
        float si = 0.0f;
        #pragma unroll
        for (int g = 0; g < NIMG_CHUNK; g++) si += g_isum[b][g];
        float sp = 0.0f;
        #pragma unroll
        for (int g = 0; g < NPAT_CHUNK; g++) sp += g_psum[b][g];
        s_s = si / 1228800.0f - sp / 270000.0f;
    }
    __syncthreads();

    // ---- phase 1: last-writer resolve per pixel ----
    int x = x0t + threadIdx.x;
    int y = y0t + threadIdx.y;
    int V = -1;
    float vpy = 0.f, vpx = 0.f;
    float fy_ = (float)y, fx_ = (float)x;
    unsigned mm = m;
    while (mm) {
        int n = __ffs(mm) - 1;
        mm &= mm - 1;
        const Geo& G = sg[n];
        float u = fy_ - G.y0i;
        float v = fx_ - G.x0i;
        if (u >= 0.f && v >= 0.f && u < G.diagi && v < G.diagi) {
            float um = u - G.cc, vm = v - G.cc;
            float py = G.cc + G.ca * um - G.sa * vm - G.top;
            float px = G.cc + G.sa * um + G.ca * vm - G.top;
            float lim = G.phi - 1.0f;
            if (py >= 0.f && py <= lim && px >= 0.f && px <= lim) {
                V = n; vpy = py; vpx = px;
            }
        }
    }

    bool heavy = (V >= 0);
    unsigned wm = __ballot_sync(0xffffffffu, heavy);
    int lane = threadIdx.x;
    int wbase = 0;
    if (wm) {
        if (lane == 0) wbase = atomicAdd(&scnt, __popc(wm));
        wbase = __shfl_sync(0xffffffffu, wbase, 0);
        if (heavy) {
            int pos = wbase + __popc(wm & ((1u << lane) - 1u));
            spy[pos] = vpy; spx[pos] = vpx;
            spk[pos] = (t << 4) | V;
        }
    }
    __syncthreads();

    // ---- phase 2: dense heavy processing, results into smem tile ----
    int cnt = scnt;
    if (t < cnt) {
        int pk = spk[t];
        int p  = pk >> 4;
        const Geo& G = sg[pk & 15];
        float py = spy[t], px = spx[t];
        int yy = y0t + (p >> 5);
        int xx = x0t + (p & 31);

        float sy = (py + 0.5f) * G.r - 0.5f;
        float sx = (px + 0.5f) * G.r - 0.5f;
        float fy = floorf(sy), fx = floorf(sx);
        float wy = sy - fy, wx = sx - fx;
        int y0c = min(max((int)fy, 0), PHp - 1);
        int y1c = min(y0c + 1, PHp - 1);
        int x0c = min(max((int)fx, 0), PWp - 1);
        int x1c = min(x0c + 1, PWp - 1);
        int o00 = (y0c * PWp + x0c) * 3;
        int o01 = (y0c * PWp + x1c) * 3;
        int o10 = (y1c * PWp + x0c) * 3;
        int o11 = (y1c * PWp + x1c) * 3;

        uint32_t nb = ((uint32_t)yy * (uint32_t)Wim + (uint32_t)xx) * 3u;
        uint32_t bits[3];
        tf3(G.k2a, G.k2b, nb, bits);

        float s = s_s;
        float omy = 1.0f - wy, omx = 1.0f - wx;
        float w00 = omy * omx, w01 = omy * wx, w10 = wy * omx, w11 = wy * wx;
        #pragma unroll
        for (int c = 0; c < 3; c++) {
            float wc = g_w[b][c], bc = g_bj[b][c];
#define ADJ(pp) fminf(fmaxf(fminf(fmaxf(fmaf(wc, (pp), bc), -1.f), 1.f) + s, -1.f), 1.f)
            float samp = ADJ(patch[o00 + c]) * w00 + ADJ(patch[o01 + c]) * w01
                       + ADJ(patch[o10 + c]) * w10 + ADJ(patch[o11 + c]) * w11;
#undef ADJ
            float noise = fmaxf(-0.1f, fmaf(bits_to_unit(bits[c]), 0.2f, -0.1f));
            float res = fminf(fmaxf(samp + noise + G.bright, -1.0f), 1.0f);
            float orig = simg[p * 3 + c];
            simg[p * 3 + c] = res;
            smsk[p * 3 + c] = orig - res;
        }
    }
    __syncthreads();

    // ---- coalesced float4 writeout of both planes ----
    if (t < 192) {
        int r = t / 24, c = t % 24;
        size_t f4 = ((((size_t)(b * Him + y0t + r)) * Wim + x0t) * 3) >> 2;
        ((float4*)oimg)[f4 + c]  = ((const float4*)simg)[r * 24 + c];
        ((float4*)omask)[f4 + c] = ((const float4*)smsk)[r * 24 + c];
    }
}

// ---------------------------------------------------------------------------
extern "C" void kernel_launch(void* const* d_in, const int* in_sizes, int n_in,
                              void* d_out, int out_size) {
    const float* boxes  = (const float*)d_in[0];
    const float* images = (const float*)d_in[1];
    const float* patch  = (const float*)d_in[2];
    const float* scale  = (const float*)d_in[3];
    float* out   = (float*)d_out;
    float* omask = out + (size_t)Bimg * Him * Wim * 3;

    k_sums<<<dim3(NIMG_CHUNK + NPAT_CHUNK + 1, 16), 256>>>(images, patch, boxes, scale);
    k_main<<<dim3(20, 80, 16), dim3(32, 8)>>>(images, patch, out, omask);

    (void)in_sizes; (void)n_in; (void)out_size;
}

// round 6
// speedup vs baseline: 1.0606x; 1.0606x over previous
#include <cuda_runtime.h>
#include <stdint.h>
#include <math.h>

#define Bimg 16
#define Nbox 16
#define Him  640
#define Wim  640
#define PHp  300
#define PWp  300
#define PTOT (PHp*PWp*3)

// ---------------------------------------------------------------------------
// JAX threefry2x32 (20 rounds), partitionable random-bits convention
// ---------------------------------------------------------------------------
__device__ __forceinline__ void tf2x32(uint32_t k0, uint32_t k1,
                                       uint32_t x0, uint32_t x1,
                                       uint32_t& o0, uint32_t& o1) {
    uint32_t ks2 = k0 ^ k1 ^ 0x1BD11BDAu;
    x0 += k0; x1 += k1;
#define TF_RND(r) { x0 += x1; x1 = __funnelshift_l(x1, x1, (r)); x1 ^= x0; }
    TF_RND(13) TF_RND(15) TF_RND(26) TF_RND(6)
    x0 += k1;  x1 += ks2 + 1u;
    TF_RND(17) TF_RND(29) TF_RND(16) TF_RND(24)
    x0 += ks2; x1 += k0 + 2u;
    TF_RND(13) TF_RND(15) TF_RND(26) TF_RND(6)
    x0 += k0;  x1 += k1 + 3u;
    TF_RND(17) TF_RND(29) TF_RND(16) TF_RND(24)
    x0 += k1;  x1 += ks2 + 4u;
    TF_RND(13) TF_RND(15) TF_RND(26) TF_RND(6)
    x0 += ks2; x1 += k0 + 5u;
#undef TF_RND
    o0 = x0; o1 = x1;
}

__device__ __forceinline__ uint32_t rbits(uint32_t k0, uint32_t k1, uint64_t idx) {
    uint32_t a, b;
    tf2x32(k0, k1, (uint32_t)(idx >> 32), (uint32_t)idx, a, b);
    return a ^ b;
}

// 3 interleaved threefry chains, counters (c0, c0+1, c0+2), hi word = 0.
__device__ __forceinline__ void tf3(uint32_t k0, uint32_t k1, uint32_t c0,
                                    uint32_t out[3]) {
    uint32_t ks2 = k0 ^ k1 ^ 0x1BD11BDAu;
    uint32_t a0 = k0, a1 = k0, a2 = k0;
    uint32_t b0 = c0 + k1, b1 = c0 + 1u + k1, b2 = c0 + 2u + k1;
#define R3(r)  { a0 += b0; b0 = __funnelshift_l(b0,b0,(r)); b0 ^= a0; \
                 a1 += b1; b1 = __funnelshift_l(b1,b1,(r)); b1 ^= a1; \
                 a2 += b2; b2 = __funnelshift_l(b2,b2,(r)); b2 ^= a2; }
#define INJ3(ka, kb) { a0 += (ka); b0 += (kb); a1 += (ka); b1 += (kb); a2 += (ka); b2 += (kb); }
    R3(13) R3(15) R3(26) R3(6)
    INJ3(k1, ks2 + 1u)
    R3(17) R3(29) R3(16) R3(24)
    INJ3(ks2, k0 + 2u)
    R3(13) R3(15) R3(26) R3(6)
    INJ3(k0, k1 + 3u)
    R3(17) R3(29) R3(16) R3(24)
    INJ3(k1, ks2 + 4u)
    R3(13) R3(15) R3(26) R3(6)
    out[0] = (a0 + ks2) ^ (b0 + k0 + 5u);
    out[1] = (a1 + ks2) ^ (b1 + k0 + 5u);
    out[2] = (a2 + ks2) ^ (b2 + k0 + 5u);
#undef R3
#undef INJ3
}

__device__ __forceinline__ float bits_to_unit(uint32_t bits) {
    return __uint_as_float((bits >> 9) | 0x3f800000u) - 1.0f;
}

__device__ __forceinline__ float juniform(uint32_t k0, uint32_t k1, uint64_t i,
                                          float lo, float hi) {
    float f = bits_to_unit(rbits(k0, k1, i));
    return fmaxf(lo, f * (hi - lo) + lo);
}

__device__ __forceinline__ float erfinv_xla(float x) {
    float w = -log1pf(-x * x);
    float p;
    if (w < 5.0f) {
        w -= 2.5f;
        p = 2.81022636e-08f;
        p = fmaf(p, w, 3.43273939e-07f);
        p = fmaf(p, w, -3.5233877e-06f);
        p = fmaf(p, w, -4.39150654e-06f);
        p = fmaf(p, w, 0.00021858087f);
        p = fmaf(p, w, -0.00125372503f);
        p = fmaf(p, w, -0.00417768164f);
        p = fmaf(p, w, 0.246640727f);
        p = fmaf(p, w, 1.50140941f);
    } else {
        w = sqrtf(w) - 3.0f;
        p = -0.000200214257f;
        p = fmaf(p, w, 0.000100950558f);
        p = fmaf(p, w, 0.00134934322f);
        p = fmaf(p, w, -0.00367342844f);
        p = fmaf(p, w, 0.00573950773f);
        p = fmaf(p, w, -0.0076224613f);
        p = fmaf(p, w, 0.00943887047f);
        p = fmaf(p, w, 1.00167406f);
        p = fmaf(p, w, 2.83297682f);
    }
    return p * x;
}

__device__ __forceinline__ float jnormal(uint32_t k0, uint32_t k1, uint64_t i) {
    const float lo = -0.99999994f;
    float u = juniform(k0, k1, i, lo, 1.0f);
    return 1.41421354f * erfinv_xla(u);
}

__device__ __forceinline__ void wb_for(int b, float w[3], float bb[3]) {
    uint32_t ib0, ib1;
    tf2x32(0u, 42u, 0u, (uint32_t)b, ib0, ib1);
    uint32_t kw0, kw1, kB0, kB1;
    tf2x32(ib0, ib1, 0u, 0u, kw0, kw1);
    tf2x32(ib0, ib1, 0u, 1u, kB0, kB1);
    #pragma unroll
    for (int c = 0; c < 3; c++) {
        w[c]  = jnormal(kw0, kw1, (uint64_t)c) * 0.1f + 0.5f;
        bb[c] = jnormal(kB0, kB1, (uint64_t)c) * 0.01f;
    }
}

// ---------------------------------------------------------------------------
// Device scratch
// ---------------------------------------------------------------------------
struct Geo {
    float y0i, x0i, diagi, phi, cc, top, r, ca, sa, bright;
    uint32_t k2a, k2b;
    int valid;
    int pad;
};                                      // 14 words

#define NIMG_CHUNK 32
#define NPAT_CHUNK 8

__device__ Geo   g_geo[Bimg][Nbox];
__device__ float g_w[Bimg][3];
__device__ float g_bj[Bimg][3];
__device__ float g_isum[Bimg][NIMG_CHUNK];
__device__ float g_psum[Bimg][NPAT_CHUNK];

// ---------------------------------------------------------------------------
// K1: fused setup + sums (f32, 4-stream MLP). grid (41, 16), 256 thr.
// ---------------------------------------------------------------------------
__global__ void k_sums(const float* __restrict__ images,
                       const float* __restrict__ patch,
                       const float* __restrict__ boxes,
                       const float* __restrict__ scale_p) {
    int b = blockIdx.y, g = blockIdx.x;

    if (g == NIMG_CHUNK + NPAT_CHUNK) {
        int n = threadIdx.x;
        if (n == 0) {
            float w[3], bb[3];
            wb_for(b, w, bb);
            #pragma unroll
            for (int c = 0; c < 3; c++) { g_w[b][c] = w[c]; g_bj[b][c] = bb[c]; }
        }
        if (n < Nbox) {
            float scale = scale_p[0];
            uint32_t ib0, ib1, kl0, kl1;
            tf2x32(0u, 42u, 0u, (uint32_t)b, ib0, ib1);
            tf2x32(ib0, ib1, 0u, 2u, kl0, kl1);
            uint32_t kn0, kn1;
            tf2x32(kl0, kl1, 0u, (uint32_t)n, kn0, kn1);
            uint32_t k10, k11, k20, k21, k30, k31;
            tf2x32(kn0, kn1, 0u, 0u, k10, k11);
            tf2x32(kn0, kn1, 0u, 1u, k20, k21);
            tf2x32(kn0, kn1, 0u, 2u, k30, k31);

            const float MAXA = (float)(20.0 * 3.14159265358979323846 / 180.0);
            float angle  = juniform(k10, k11, 0ull, -MAXA, MAXA);
            float bright = juniform(k30, k31, 0ull, -0.3f, 0.3f);

            const float* bx = boxes + ((size_t)b * Nbox + n) * 4;
            float ymin = bx[0], xmin = bx[1], ymax = bx[2], xmax = bx[3];
            float h  = ymax - ymin;
            float ww = xmax - xmin;
            float longer = fmaxf(h, ww);
            float ps   = floorf(longer * scale);
            float diag = fminf(sqrtf(2.0f) * ps, (float)Wim);
            float oy = ymin + h * 0.5f;
            float ox = xmin + ww * 0.5f;
            float y0 = fmaxf(oy - diag * 0.5f, 0.0f);
            float x0 = fmaxf(ox - diag * 0.5f, 0.0f);
            y0 = (y0 + diag > (float)Him) ? ((float)Him - diag) : y0;
            x0 = (x0 + diag > (float)Wim) ? ((float)Wim - diag) : x0;
            float phi   = fmaxf(floorf(ps), 1.0f);
            float diagi = floorf(diag);

            Geo gg;
            gg.y0i = floorf(y0); gg.x0i = floorf(x0);
            gg.diagi = diagi; gg.phi = phi;
            gg.cc  = (diagi - 1.0f) * 0.5f;
            gg.top = floorf((diagi - phi) * 0.5f);
            gg.r   = 300.0f / phi;
            gg.ca  = cosf(angle);
            gg.sa  = sinf(angle);
            gg.bright = bright;
            gg.k2a = k20; gg.k2b = k21;
            gg.valid = (phi * phi > 60.0f) ? 1 : 0;
            gg.pad = 0;
            g_geo[b][n] = gg;
        }
        return;
    }

    float acc = 0.0f;
    if (g < NIMG_CHUNK) {
        const size_t IMG = (size_t)Him * Wim * 3;
        size_t base = (size_t)b * IMG + (size_t)g * (IMG / NIMG_CHUNK);
        const float4* src = (const float4*)(images + base);
        const int nvec = (int)((IMG / NIMG_CHUNK) / 4);   // 9600 float4s
        float a0 = 0.f, a1 = 0.f, a2 = 0.f, a3 = 0.f;
        float a4 = 0.f, a5 = 0.f, a6 = 0.f, a7 = 0.f;
        float a8 = 0.f, a9 = 0.f, aa = 0.f, ab = 0.f;
        float ac = 0.f, ad = 0.f, ae = 0.f, af = 0.f;
        int i = threadIdx.x;
        for (; i + 768 < nvec; i += 1024) {
            float4 v0 = src[i];
            float4 v1 = src[i + 256];
            float4 v2 = src[i + 512];
            float4 v3 = src[i + 768];
            a0 += v0.x; a1 += v0.y; a2 += v0.z; a3 += v0.w;
            a4 += v1.x; a5 += v1.y; a6 += v1.z; a7 += v1.w;
            a8 += v2.x; a9 += v2.y; aa += v2.z; ab += v2.w;
            ac += v3.x; ad += v3.y; ae += v3.z; af += v3.w;
        }
        for (; i < nvec; i += 256) {
            float4 v = src[i];
            a0 += v.x; a1 += v.y; a2 += v.z; a3 += v.w;
        }
        acc = (((a0 + a1) + (a2 + a3)) + ((a4 + a5) + (a6 + a7)))
            + (((a8 + a9) + (aa + ab)) + ((ac + ad) + (ae + af)));
    } else {
        float w[3], bb[3];
        wb_for(b, w, bb);
        int gp = g - NIMG_CHUNK;
        int chunk = PTOT / NPAT_CHUNK;                    // 33750
        int base = gp * chunk;
        float a0 = 0.f, a1 = 0.f;
        int i = base + threadIdx.x;
        int end = base + chunk;
        for (; i + 256 < end; i += 512) {
            int c0 = i % 3;
            int c1 = (i + 256) % 3;
            a0 += fminf(fmaxf(w[c0] * patch[i] + bb[c0], -1.0f), 1.0f);
            a1 += fminf(fmaxf(w[c1] * patch[i + 256] + bb[c1], -1.0f), 1.0f);
        }
        if (i < end) {
            int c = i % 3;
            a0 += fminf(fmaxf(w[c] * patch[i] + bb[c], -1.0f), 1.0f);
        }
        acc = a0 + a1;
    }
    __shared__ float sh[256];
    sh[threadIdx.x] = acc;
    __syncthreads();
    for (int s = 128; s > 0; s >>= 1) {
        if (threadIdx.x < s) sh[threadIdx.x] += sh[threadIdx.x + s];
        __syncthreads();
    }
    if (threadIdx.x == 0) {
        if (g < NIMG_CHUNK) g_isum[b][g] = sh[0];
        else                g_psum[b][g - NIMG_CHUNK] = sh[0];
    }
}

// ---------------------------------------------------------------------------
// K2: main paste kernel. grid (20, 80, 16), block (32, 8).
// Direct global I/O (no tile staging); compaction for dense tf3 phase;
// on-the-fly patch adjust; warp-shuffle brightness scalar.
// ---------------------------------------------------------------------------
__global__ void k_main(const float* __restrict__ images,
                       const float* __restrict__ patch,
                       float* __restrict__ oimg,
                       float* __restrict__ omask) {
    __shared__ Geo   sg[Nbox];
    __shared__ float spy[256], spx[256];
    __shared__ float so0[256], so1[256], so2[256];
    __shared__ int   spk[256];
    __shared__ int   scnt;
    __shared__ float s_s;

    int b = blockIdx.z;
    int t = threadIdx.y * 32 + threadIdx.x;
    if (t < Nbox * 14)
        ((float*)sg)[t] = ((const float*)&g_geo[b][0])[t];
    if (t == 0) scnt = 0;
    __syncthreads();

    int x0t = blockIdx.x * 32;
    int y0t = blockIdx.y * 8;
    float tx0 = (float)x0t;
    float ty0 = (float)y0t;

    unsigned m = 0;
    #pragma unroll
    for (int n = 0; n < Nbox; n++) {
        const Geo& G = sg[n];
        bool ov = G.valid &&
                  (ty0 + 8.0f > G.y0i) && (ty0 < G.y0i + G.diagi) &&
                  (tx0 + 32.0f > G.x0i) && (tx0 < G.x0i + G.diagi);
        if (ov) m |= (1u << n);
    }

    if (m == 0) {
        // fast path: float4 copy + zero (tile is 768 floats = 192 float4)
        if (t < 192) {
            int r = t / 24, c = t % 24;
            size_t f4 = ((((size_t)(b * Him + y0t + r)) * Wim + x0t) * 3) >> 2;
            float4 v = ((const float4*)images)[f4 + c];
            ((float4*)oimg)[f4 + c]  = v;
            ((float4*)omask)[f4 + c] = make_float4(0.f, 0.f, 0.f, 0.f);
        }
        return;
    }

    // warp 0: brightness shift s via shuffle reduction (no extra barrier;
    // the compaction __syncthreads below orders s_s before phase 2 reads)
    if (t < 32) {
        float si = g_isum[b][t];
        float sp = (t < NPAT_CHUNK) ? g_psum[b][t] : 0.0f;
        #pragma unroll
        for (int o = 16; o > 0; o >>= 1) {
            si += __shfl_down_sync(0xffffffffu, si, o);
            sp += __shfl_down_sync(0xffffffffu, sp, o);
        }
        if (t == 0) s_s = si / 1228800.0f - sp / 270000.0f;
    }

    // ---- phase 1: last-writer resolve per pixel ----
    int x = x0t + threadIdx.x;
    int y = y0t + threadIdx.y;
    size_t base = (((size_t)b * Him + y) * Wim + x) * 3;
    float o0 = images[base], o1 = images[base + 1], o2 = images[base + 2];

    int V = -1;
    float vpy = 0.f, vpx = 0.f;
    float fy_ = (float)y, fx_ = (float)x;
    unsigned mm = m;
    while (mm) {
        int n = __ffs(mm) - 1;
        mm &= mm - 1;
        const Geo& G = sg[n];
        float u = fy_ - G.y0i;
        float v = fx_ - G.x0i;
        if (u >= 0.f && v >= 0.f && u < G.diagi && v < G.diagi) {
            float um = u - G.cc, vm = v - G.cc;
            float py = G.cc + G.ca * um - G.sa * vm - G.top;
            float px = G.cc + G.sa * um + G.ca * vm - G.top;
            float lim = G.phi - 1.0f;
            if (py >= 0.f && py <= lim && px >= 0.f && px <= lim) {
                V = n; vpy = py; vpx = px;
            }
        }
    }

    bool heavy = (V >= 0);
    if (!heavy) {
        oimg[base] = o0; oimg[base + 1] = o1; oimg[base + 2] = o2;
        omask[base] = 0.f; omask[base + 1] = 0.f; omask[base + 2] = 0.f;
    } else {
        so0[t] = o0; so1[t] = o1; so2[t] = o2;
    }

    unsigned wm = __ballot_sync(0xffffffffu, heavy);
    int lane = threadIdx.x;
    int wbase = 0;
    if (wm) {
        if (lane == 0) wbase = atomicAdd(&scnt, __popc(wm));
        wbase = __shfl_sync(0xffffffffu, wbase, 0);
        if (heavy) {
            int pos = wbase + __popc(wm & ((1u << lane) - 1u));
            spy[pos] = vpy; spx[pos] = vpx;
            spk[pos] = (t << 4) | V;
        }
    }
    __syncthreads();

    // ---- phase 2: dense heavy processing, direct stores ----
    int cnt = scnt;
    if (t < cnt) {
        int pk = spk[t];
        int p  = pk >> 4;
        const Geo& G = sg[pk & 15];
        float py = spy[t], px = spx[t];
        int yy = y0t + (p >> 5);
        int xx = x0t + (p & 31);

        float sy = (py + 0.5f) * G.r - 0.5f;
        float sx = (px + 0.5f) * G.r - 0.5f;
        float fy = floorf(sy), fx = floorf(sx);
        float wy = sy - fy, wx = sx - fx;
        int y0c = min(max((int)fy, 0), PHp - 1);
        int y1c = min(y0c + 1, PHp - 1);
        int x0c = min(max((int)fx, 0), PWp - 1);
        int x1c = min(x0c + 1, PWp - 1);
        int o00 = (y0c * PWp + x0c) * 3;
        int o01 = (y0c * PWp + x1c) * 3;
        int o10 = (y1c * PWp + x0c) * 3;
        int o11 = (y1c * PWp + x1c) * 3;

        uint32_t nb = ((uint32_t)yy * (uint32_t)Wim + (uint32_t)xx) * 3u;
        uint32_t bits[3];
        tf3(G.k2a, G.k2b, nb, bits);

        float s = s_s;
        float omy = 1.0f - wy, omx = 1.0f - wx;
        float w00 = omy * omx, w01 = omy * wx, w10 = wy * omx, w11 = wy * wx;
        float res[3];
        #pragma unroll
        for (int c = 0; c < 3; c++) {
            float wc = g_w[b][c], bc = g_bj[b][c];
#define ADJ(pp) fminf(fmaxf(fminf(fmaxf(fmaf(wc, (pp), bc), -1.f), 1.f) + s, -1.f), 1.f)
            float samp = ADJ(patch[o00 + c]) * w00 + ADJ(patch[o01 + c]) * w01
                       + ADJ(patch[o10 + c]) * w10 + ADJ(patch[o11 + c]) * w11;
#undef ADJ
            float noise = fmaxf(-0.1f, fmaf(bits_to_unit(bits[c]), 0.2f, -0.1f));
            res[c] = fminf(fmaxf(samp + noise + G.bright, -1.0f), 1.0f);
        }

        size_t hb = (((size_t)b * Him + yy) * Wim + xx) * 3;
        oimg[hb]      = res[0]; oimg[hb + 1]  = res[1]; oimg[hb + 2]  = res[2];
        omask[hb]     = so0[p] - res[0];
        omask[hb + 1] = so1[p] - res[1];
        omask[hb + 2] = so2[p] - res[2];
    }
}

// ---------------------------------------------------------------------------
extern "C" void kernel_launch(void* const* d_in, const int* in_sizes, int n_in,
                              void* d_out, int out_size) {
    const float* boxes  = (const float*)d_in[0];
    const float* images = (const float*)d_in[1];
    const float* patch  = (const float*)d_in[2];
    const float* scale  = (const float*)d_in[3];
    float* out   = (float*)d_out;
    float* omask = out + (size_t)Bimg * Him * Wim * 3;

    k_sums<<<dim3(NIMG_CHUNK + NPAT_CHUNK + 1, 16), 256>>>(images, patch, boxes, scale);
    k_main<<<dim3(20, 80, 16), dim3(32, 8)>>>(images, patch, out, omask);

    (void)in_sizes; (void)n_in; (void)out_size;
}

// round 7
// speedup vs baseline: 1.3478x; 1.2708x over previous
#include <cuda_runtime.h>
#include <stdint.h>
#include <math.h>

#define Bimg 16
#define Nbox 16
#define Him  640
#define Wim  640
#define PHp  300
#define PWp  300
#define PTOT (PHp*PWp*3)
#define IMG  ((size_t)Him * Wim * 3)

// ---------------------------------------------------------------------------
// JAX threefry2x32 (20 rounds), partitionable random-bits convention
// ---------------------------------------------------------------------------
__device__ __forceinline__ void tf2x32(uint32_t k0, uint32_t k1,
                                       uint32_t x0, uint32_t x1,
                                       uint32_t& o0, uint32_t& o1) {
    uint32_t ks2 = k0 ^ k1 ^ 0x1BD11BDAu;
    x0 += k0; x1 += k1;
#define TF_RND(r) { x0 += x1; x1 = __funnelshift_l(x1, x1, (r)); x1 ^= x0; }
    TF_RND(13) TF_RND(15) TF_RND(26) TF_RND(6)
    x0 += k1;  x1 += ks2 + 1u;
    TF_RND(17) TF_RND(29) TF_RND(16) TF_RND(24)
    x0 += ks2; x1 += k0 + 2u;
    TF_RND(13) TF_RND(15) TF_RND(26) TF_RND(6)
    x0 += k0;  x1 += k1 + 3u;
    TF_RND(17) TF_RND(29) TF_RND(16) TF_RND(24)
    x0 += k1;  x1 += ks2 + 4u;
    TF_RND(13) TF_RND(15) TF_RND(26) TF_RND(6)
    x0 += ks2; x1 += k0 + 5u;
#undef TF_RND
    o0 = x0; o1 = x1;
}

__device__ __forceinline__ uint32_t rbits(uint32_t k0, uint32_t k1, uint64_t idx) {
    uint32_t a, b;
    tf2x32(k0, k1, (uint32_t)(idx >> 32), (uint32_t)idx, a, b);
    return a ^ b;
}

// 3 interleaved threefry chains, counters (c0, c0+1, c0+2), hi word = 0.
__device__ __forceinline__ void tf3(uint32_t k0, uint32_t k1, uint32_t c0,
                                    uint32_t out[3]) {
    uint32_t ks2 = k0 ^ k1 ^ 0x1BD11BDAu;
    uint32_t a0 = k0, a1 = k0, a2 = k0;
    uint32_t b0 = c0 + k1, b1 = c0 + 1u + k1, b2 = c0 + 2u + k1;
#define R3(r)  { a0 += b0; b0 = __funnelshift_l(b0,b0,(r)); b0 ^= a0; \
                 a1 += b1; b1 = __funnelshift_l(b1,b1,(r)); b1 ^= a1; \
                 a2 += b2; b2 = __funnelshift_l(b2,b2,(r)); b2 ^= a2; }
#define INJ3(ka, kb) { a0 += (ka); b0 += (kb); a1 += (ka); b1 += (kb); a2 += (ka); b2 += (kb); }
    R3(13) R3(15) R3(26) R3(6)
    INJ3(k1, ks2 + 1u)
    R3(17) R3(29) R3(16) R3(24)
    INJ3(ks2, k0 + 2u)
    R3(13) R3(15) R3(26) R3(6)
    INJ3(k0, k1 + 3u)
    R3(17) R3(29) R3(16) R3(24)
    INJ3(k1, ks2 + 4u)
    R3(13) R3(15) R3(26) R3(6)
    out[0] = (a0 + ks2) ^ (b0 + k0 + 5u);
    out[1] = (a1 + ks2) ^ (b1 + k0 + 5u);
    out[2] = (a2 + ks2) ^ (b2 + k0 + 5u);
#undef R3
#undef INJ3
}

__device__ __forceinline__ float bits_to_unit(uint32_t bits) {
    return __uint_as_float((bits >> 9) | 0x3f800000u) - 1.0f;
}

__device__ __forceinline__ float juniform(uint32_t k0, uint32_t k1, uint64_t i,
                                          float lo, float hi) {
    float f = bits_to_unit(rbits(k0, k1, i));
    return fmaxf(lo, f * (hi - lo) + lo);
}

__device__ __forceinline__ float erfinv_xla(float x) {
    float w = -log1pf(-x * x);
    float p;
    if (w < 5.0f) {
        w -= 2.5f;
        p = 2.81022636e-08f;
        p = fmaf(p, w, 3.43273939e-07f);
        p = fmaf(p, w, -3.5233877e-06f);
        p = fmaf(p, w, -4.39150654e-06f);
        p = fmaf(p, w, 0.00021858087f);
        p = fmaf(p, w, -0.00125372503f);
        p = fmaf(p, w, -0.00417768164f);
        p = fmaf(p, w, 0.246640727f);
        p = fmaf(p, w, 1.50140941f);
    } else {
        w = sqrtf(w) - 3.0f;
        p = -0.000200214257f;
        p = fmaf(p, w, 0.000100950558f);
        p = fmaf(p, w, 0.00134934322f);
        p = fmaf(p, w, -0.00367342844f);
        p = fmaf(p, w, 0.00573950773f);
        p = fmaf(p, w, -0.0076224613f);
        p = fmaf(p, w, 0.00943887047f);
        p = fmaf(p, w, 1.00167406f);
        p = fmaf(p, w, 2.83297682f);
    }
    return p * x;
}

__device__ __forceinline__ float jnormal(uint32_t k0, uint32_t k1, uint64_t i) {
    const float lo = -0.99999994f;
    float u = juniform(k0, k1, i, lo, 1.0f);
    return 1.41421354f * erfinv_xla(u);
}

__device__ __forceinline__ void wb_for(int b, float w[3], float bb[3]) {
    uint32_t ib0, ib1;
    tf2x32(0u, 42u, 0u, (uint32_t)b, ib0, ib1);
    uint32_t kw0, kw1, kB0, kB1;
    tf2x32(ib0, ib1, 0u, 0u, kw0, kw1);
    tf2x32(ib0, ib1, 0u, 1u, kB0, kB1);
    #pragma unroll
    for (int c = 0; c < 3; c++) {
        w[c]  = jnormal(kw0, kw1, (uint64_t)c) * 0.1f + 0.5f;
        bb[c] = jnormal(kB0, kB1, (uint64_t)c) * 0.01f;
    }
}

// ---------------------------------------------------------------------------
// Device scratch
// ---------------------------------------------------------------------------
struct Geo {
    float y0i, x0i, diagi, phi, cc, top, r, ca, sa, bright;
    uint32_t k2a, k2b;
    int valid;
    int pad;
};                                      // 14 words

#define NIMG_CHUNK 64
#define NPAT_CHUNK 8

__device__ Geo   g_geo[Bimg][Nbox];
__device__ float g_w[Bimg][3];
__device__ float g_bj[Bimg][3];
__device__ float g_isum[Bimg][NIMG_CHUNK];
__device__ float g_psum[Bimg][NPAT_CHUNK];

// ---------------------------------------------------------------------------
// K1 (k_prep): pure streaming copy+zero with fused image sums, plus patch
// sums and geometry. grid (64+8+1, 16), 256 thr.
//   x < 64  : copy images->img_out, zero mask, partial image sum (f32)
//   x 64..71: clipped-patch partial sums
//   x == 72 : per-box geometry + g_w/g_bj
// ---------------------------------------------------------------------------
__global__ void k_prep(const float* __restrict__ images,
                       const float* __restrict__ patch,
                       const float* __restrict__ boxes,
                       const float* __restrict__ scale_p,
                       float* __restrict__ oimg,
                       float* __restrict__ omask) {
    int b = blockIdx.y, g = blockIdx.x;

    if (g == NIMG_CHUNK + NPAT_CHUNK) {
        int n = threadIdx.x;
        if (n == 0) {
            float w[3], bb[3];
            wb_for(b, w, bb);
            #pragma unroll
            for (int c = 0; c < 3; c++) { g_w[b][c] = w[c]; g_bj[b][c] = bb[c]; }
        }
        if (n < Nbox) {
            float scale = scale_p[0];
            uint32_t ib0, ib1, kl0, kl1;
            tf2x32(0u, 42u, 0u, (uint32_t)b, ib0, ib1);
            tf2x32(ib0, ib1, 0u, 2u, kl0, kl1);
            uint32_t kn0, kn1;
            tf2x32(kl0, kl1, 0u, (uint32_t)n, kn0, kn1);
            uint32_t k10, k11, k20, k21, k30, k31;
            tf2x32(kn0, kn1, 0u, 0u, k10, k11);
            tf2x32(kn0, kn1, 0u, 1u, k20, k21);
            tf2x32(kn0, kn1, 0u, 2u, k30, k31);

            const float MAXA = (float)(20.0 * 3.14159265358979323846 / 180.0);
            float angle  = juniform(k10, k11, 0ull, -MAXA, MAXA);
            float bright = juniform(k30, k31, 0ull, -0.3f, 0.3f);

            const float* bx = boxes + ((size_t)b * Nbox + n) * 4;
            float ymin = bx[0], xmin = bx[1], ymax = bx[2], xmax = bx[3];
            float h  = ymax - ymin;
            float ww = xmax - xmin;
            float longer = fmaxf(h, ww);
            float ps   = floorf(longer * scale);
            float diag = fminf(sqrtf(2.0f) * ps, (float)Wim);
            float oy = ymin + h * 0.5f;
            float ox = xmin + ww * 0.5f;
            float y0 = fmaxf(oy - diag * 0.5f, 0.0f);
            float x0 = fmaxf(ox - diag * 0.5f, 0.0f);
            y0 = (y0 + diag > (float)Him) ? ((float)Him - diag) : y0;
            x0 = (x0 + diag > (float)Wim) ? ((float)Wim - diag) : x0;
            float phi   = fmaxf(floorf(ps), 1.0f);
            float diagi = floorf(diag);

            Geo gg;
            gg.y0i = floorf(y0); gg.x0i = floorf(x0);
            gg.diagi = diagi; gg.phi = phi;
            gg.cc  = (diagi - 1.0f) * 0.5f;
            gg.top = floorf((diagi - phi) * 0.5f);
            gg.r   = 300.0f / phi;
            gg.ca  = cosf(angle);
            gg.sa  = sinf(angle);
            gg.bright = bright;
            gg.k2a = k20; gg.k2b = k21;
            gg.valid = (phi * phi > 60.0f) ? 1 : 0;
            gg.pad = 0;
            g_geo[b][n] = gg;
        }
        return;
    }

    float acc = 0.0f;
    if (g < NIMG_CHUNK) {
        size_t base = (size_t)b * IMG + (size_t)g * (IMG / NIMG_CHUNK);
        const float4* src  = (const float4*)(images + base);
        float4* dimg = (float4*)(oimg + base);
        float4* dmsk = (float4*)(omask + base);
        const int nvec = (int)((IMG / NIMG_CHUNK) / 4);   // 4800 float4s
        const float4 z = make_float4(0.f, 0.f, 0.f, 0.f);
        float a0 = 0.f, a1 = 0.f;
        int i = threadIdx.x;
        for (; i + 256 < nvec; i += 512) {
            float4 v = src[i];
            float4 u = src[i + 256];
            dimg[i] = v;       dimg[i + 256] = u;
            dmsk[i] = z;       dmsk[i + 256] = z;
            a0 += (v.x + v.y) + (v.z + v.w);
            a1 += (u.x + u.y) + (u.z + u.w);
        }
        if (i < nvec) {
            float4 v = src[i];
            dimg[i] = v; dmsk[i] = z;
            a0 += (v.x + v.y) + (v.z + v.w);
        }
        acc = a0 + a1;
    } else {
        float w[3], bb[3];
        wb_for(b, w, bb);
        int gp = g - NIMG_CHUNK;
        int chunk = PTOT / NPAT_CHUNK;                    // 33750
        int base = gp * chunk;
        float a0 = 0.f, a1 = 0.f;
        int i = base + threadIdx.x;
        int end = base + chunk;
        for (; i + 256 < end; i += 512) {
            int c0 = i % 3;
            int c1 = (i + 256) % 3;
            a0 += fminf(fmaxf(w[c0] * patch[i] + bb[c0], -1.0f), 1.0f);
            a1 += fminf(fmaxf(w[c1] * patch[i + 256] + bb[c1], -1.0f), 1.0f);
        }
        if (i < end) {
            int c = i % 3;
            a0 += fminf(fmaxf(w[c] * patch[i] + bb[c], -1.0f), 1.0f);
        }
        acc = a0 + a1;
    }
    __shared__ float sh[256];
    sh[threadIdx.x] = acc;
    __syncthreads();
    for (int s = 128; s > 0; s >>= 1) {
        if (threadIdx.x < s) sh[threadIdx.x] += sh[threadIdx.x + s];
        __syncthreads();
    }
    if (threadIdx.x == 0) {
        if (g < NIMG_CHUNK) g_isum[b][g] = sh[0];
        else                g_psum[b][g - NIMG_CHUNK] = sh[0];
    }
}

// ---------------------------------------------------------------------------
// K2 (k_heavy): per-box tiles; pixel written iff this box is its LAST
// valid-src writer. grid (8, 8, 256), block (16, 16).
// ---------------------------------------------------------------------------
__global__ void k_heavy(const float* __restrict__ images,
                        const float* __restrict__ patch,
                        float* __restrict__ oimg,
                        float* __restrict__ omask) {
    int bz = blockIdx.z;
    int b = bz >> 4, n = bz & 15;

    // cheap block-uniform reject before any smem work
    const float* graw = (const float*)&g_geo[b][0];
    float diagi_n = graw[n * 14 + 2];
    int   valid_n = ((const int*)graw)[n * 14 + 12];
    int ty0 = blockIdx.y * 16, tx0 = blockIdx.x * 16;
    if (!valid_n || (float)ty0 >= diagi_n || (float)tx0 >= diagi_n) return;

    __shared__ Geo   sg[Nbox];
    __shared__ float s_s;
    int t = threadIdx.y * 16 + threadIdx.x;
    if (t < Nbox * 14)
        ((float*)sg)[t] = graw[t];
    if (t >= 224 && t < 256) {          // warp 7: brightness scalar
        int l = t - 224;
        float si = g_isum[b][l] + g_isum[b][l + 32];
        float sp = (l < NPAT_CHUNK) ? g_psum[b][l] : 0.0f;
        #pragma unroll
        for (int o = 16; o > 0; o >>= 1) {
            si += __shfl_down_sync(0xffffffffu, si, o);
            sp += __shfl_down_sync(0xffffffffu, sp, o);
        }
        if (l == 0) s_s = si / 1228800.0f - sp / 270000.0f;
    }
    __syncthreads();

    Geo G = sg[n];
    // block-uniform mask of LATER boxes overlapping this tile
    float aty0 = G.y0i + (float)ty0;
    float atx0 = G.x0i + (float)tx0;
    unsigned mj = 0;
    for (int j = n + 1; j < Nbox; j++) {
        const Geo& J = sg[j];
        if (J.valid &&
            aty0 + 16.0f > J.y0i && aty0 < J.y0i + J.diagi &&
            atx0 + 16.0f > J.x0i && atx0 < J.x0i + J.diagi)
            mj |= 1u << j;
    }

    int u = ty0 + threadIdx.y;
    int v = tx0 + threadIdx.x;
    float uf = (float)u, vf = (float)v;
    if (uf >= G.diagi || vf >= G.diagi) return;

    // valid_src for box n
    float um = uf - G.cc, vm = vf - G.cc;
    float py = G.cc + G.ca * um - G.sa * vm - G.top;
    float px = G.cc + G.sa * um + G.ca * vm - G.top;
    float lim = G.phi - 1.0f;
    if (!(py >= 0.0f && py <= lim && px >= 0.0f && px <= lim)) return;

    // skip if any LATER box also writes this pixel
    float yab = G.y0i + uf, xab = G.x0i + vf;
    unsigned mm = mj;
    while (mm) {
        int j = __ffs(mm) - 1;
        mm &= mm - 1;
        const Geo& J = sg[j];
        float uj = yab - J.y0i, vj = xab - J.x0i;
        if (uj >= 0.f && vj >= 0.f && uj < J.diagi && vj < J.diagi) {
            float umj = uj - J.cc, vmj = vj - J.cc;
            float pyj = J.cc + J.ca * umj - J.sa * vmj - J.top;
            float pxj = J.cc + J.sa * umj + J.ca * vmj - J.top;
            float lj = J.phi - 1.0f;
            if (pyj >= 0.f && pyj <= lj && pxj >= 0.f && pxj <= lj) return;
        }
    }

    // this box is the final writer: bilinear sample + jitter + noise
    int y = (int)G.y0i + u;
    int x = (int)G.x0i + v;

    float sy = (py + 0.5f) * G.r - 0.5f;
    float sx = (px + 0.5f) * G.r - 0.5f;
    float fy = floorf(sy), fx = floorf(sx);
    float wy = sy - fy, wx = sx - fx;
    int y0c = min(max((int)fy, 0), PHp - 1);
    int y1c = min(y0c + 1, PHp - 1);
    int x0c = min(max((int)fx, 0), PWp - 1);
    int x1c = min(x0c + 1, PWp - 1);
    int o00 = (y0c * PWp + x0c) * 3;
    int o01 = (y0c * PWp + x1c) * 3;
    int o10 = (y1c * PWp + x0c) * 3;
    int o11 = (y1c * PWp + x1c) * 3;

    uint32_t nb = ((uint32_t)y * (uint32_t)Wim + (uint32_t)x) * 3u;
    uint32_t bits[3];
    tf3(G.k2a, G.k2b, nb, bits);

    float s = s_s;
    float omy = 1.0f - wy, omx = 1.0f - wx;
    float w00 = omy * omx, w01 = omy * wx, w10 = wy * omx, w11 = wy * wx;
    size_t base = (((size_t)b * Him + y) * Wim + x) * 3;
    float res[3];
    #pragma unroll
    for (int c = 0; c < 3; c++) {
        float wc = g_w[b][c], bc = g_bj[b][c];
#define ADJ(pp) fminf(fmaxf(fminf(fmaxf(fmaf(wc, (pp), bc), -1.f), 1.f) + s, -1.f), 1.f)
        float samp = ADJ(patch[o00 + c]) * w00 + ADJ(patch[o01 + c]) * w01
                   + ADJ(patch[o10 + c]) * w10 + ADJ(patch[o11 + c]) * w11;
#undef ADJ
        float noise = fmaxf(-0.1f, fmaf(bits_to_unit(bits[c]), 0.2f, -0.1f));
        res[c] = fminf(fmaxf(samp + noise + G.bright, -1.0f), 1.0f);
    }

    float i0 = images[base], i1 = images[base + 1], i2 = images[base + 2];
    oimg[base]      = res[0]; oimg[base + 1]  = res[1]; oimg[base + 2]  = res[2];
    omask[base]     = i0 - res[0];
    omask[base + 1] = i1 - res[1];
    omask[base + 2] = i2 - res[2];
}

// ---------------------------------------------------------------------------
extern "C" void kernel_launch(void* const* d_in, const int* in_sizes, int n_in,
                              void* d_out, int out_size) {
    const float* boxes  = (const float*)d_in[0];
    const float* images = (const float*)d_in[1];
    const float* patch  = (const float*)d_in[2];
    const float* scale  = (const float*)d_in[3];
    float* out   = (float*)d_out;
    float* omask = out + (size_t)Bimg * IMG;

    k_prep<<<dim3(NIMG_CHUNK + NPAT_CHUNK + 1, 16), 256>>>(
        images, patch, boxes, scale, out, omask);
    k_heavy<<<dim3(8, 8, Bimg * Nbox), dim3(16, 16)>>>(
        images, patch, out, omask);

    (void)in_sizes; (void)n_in; (void)out_size;
}

// round 8
// speedup vs baseline: 1.4151x; 1.0499x over previous
#include <cuda_runtime.h>
#include <stdint.h>
#include <math.h>

#define Bimg 16
#define Nbox 16
#define Him  640
#define Wim  640
#define PHp  300
#define PWp  300
#define PTOT (PHp*PWp*3)
#define IMG  ((size_t)Him * Wim * 3)

// ---------------------------------------------------------------------------
// JAX threefry2x32 (20 rounds), partitionable random-bits convention
// ---------------------------------------------------------------------------
__device__ __forceinline__ void tf2x32(uint32_t k0, uint32_t k1,
                                       uint32_t x0, uint32_t x1,
                                       uint32_t& o0, uint32_t& o1) {
    uint32_t ks2 = k0 ^ k1 ^ 0x1BD11BDAu;
    x0 += k0; x1 += k1;
#define TF_RND(r) { x0 += x1; x1 = __funnelshift_l(x1, x1, (r)); x1 ^= x0; }
    TF_RND(13) TF_RND(15) TF_RND(26) TF_RND(6)
    x0 += k1;  x1 += ks2 + 1u;
    TF_RND(17) TF_RND(29) TF_RND(16) TF_RND(24)
    x0 += ks2; x1 += k0 + 2u;
    TF_RND(13) TF_RND(15) TF_RND(26) TF_RND(6)
    x0 += k0;  x1 += k1 + 3u;
    TF_RND(17) TF_RND(29) TF_RND(16) TF_RND(24)
    x0 += k1;  x1 += ks2 + 4u;
    TF_RND(13) TF_RND(15) TF_RND(26) TF_RND(6)
    x0 += ks2; x1 += k0 + 5u;
#undef TF_RND
    o0 = x0; o1 = x1;
}

__device__ __forceinline__ uint32_t rbits(uint32_t k0, uint32_t k1, uint64_t idx) {
    uint32_t a, b;
    tf2x32(k0, k1, (uint32_t)(idx >> 32), (uint32_t)idx, a, b);
    return a ^ b;
}

// 3 interleaved threefry chains, counters (c0, c0+1, c0+2), hi word = 0.
__device__ __forceinline__ void tf3(uint32_t k0, uint32_t k1, uint32_t c0,
                                    uint32_t out[3]) {
    uint32_t ks2 = k0 ^ k1 ^ 0x1BD11BDAu;
    uint32_t a0 = k0, a1 = k0, a2 = k0;
    uint32_t b0 = c0 + k1, b1 = c0 + 1u + k1, b2 = c0 + 2u + k1;
#define R3(r)  { a0 += b0; b0 = __funnelshift_l(b0,b0,(r)); b0 ^= a0; \
                 a1 += b1; b1 = __funnelshift_l(b1,b1,(r)); b1 ^= a1; \
                 a2 += b2; b2 = __funnelshift_l(b2,b2,(r)); b2 ^= a2; }
#define INJ3(ka, kb) { a0 += (ka); b0 += (kb); a1 += (ka); b1 += (kb); a2 += (ka); b2 += (kb); }
    R3(13) R3(15) R3(26) R3(6)
    INJ3(k1, ks2 + 1u)
    R3(17) R3(29) R3(16) R3(24)
    INJ3(ks2, k0 + 2u)
    R3(13) R3(15) R3(26) R3(6)
    INJ3(k0, k1 + 3u)
    R3(17) R3(29) R3(16) R3(24)
    INJ3(k1, ks2 + 4u)
    R3(13) R3(15) R3(26) R3(6)
    out[0] = (a0 + ks2) ^ (b0 + k0 + 5u);
    out[1] = (a1 + ks2) ^ (b1 + k0 + 5u);
    out[2] = (a2 + ks2) ^ (b2 + k0 + 5u);
#undef R3
#undef INJ3
}

__device__ __forceinline__ float bits_to_unit(uint32_t bits) {
    return __uint_as_float((bits >> 9) | 0x3f800000u) - 1.0f;
}

__device__ __forceinline__ float juniform(uint32_t k0, uint32_t k1, uint64_t i,
                                          float lo, float hi) {
    float f = bits_to_unit(rbits(k0, k1, i));
    return fmaxf(lo, f * (hi - lo) + lo);
}

__device__ __forceinline__ float erfinv_xla(float x) {
    float w = -log1pf(-x * x);
    float p;
    if (w < 5.0f) {
        w -= 2.5f;
        p = 2.81022636e-08f;
        p = fmaf(p, w, 3.43273939e-07f);
        p = fmaf(p, w, -3.5233877e-06f);
        p = fmaf(p, w, -4.39150654e-06f);
        p = fmaf(p, w, 0.00021858087f);
        p = fmaf(p, w, -0.00125372503f);
        p = fmaf(p, w, -0.00417768164f);
        p = fmaf(p, w, 0.246640727f);
        p = fmaf(p, w, 1.50140941f);
    } else {
        w = sqrtf(w) - 3.0f;
        p = -0.000200214257f;
        p = fmaf(p, w, 0.000100950558f);
        p = fmaf(p, w, 0.00134934322f);
        p = fmaf(p, w, -0.00367342844f);
        p = fmaf(p, w, 0.00573950773f);
        p = fmaf(p, w, -0.0076224613f);
        p = fmaf(p, w, 0.00943887047f);
        p = fmaf(p, w, 1.00167406f);
        p = fmaf(p, w, 2.83297682f);
    }
    return p * x;
}

__device__ __forceinline__ float jnormal(uint32_t k0, uint32_t k1, uint64_t i) {
    const float lo = -0.99999994f;
    float u = juniform(k0, k1, i, lo, 1.0f);
    return 1.41421354f * erfinv_xla(u);
}

__device__ __forceinline__ void wb_for(int b, float w[3], float bb[3]) {
    uint32_t ib0, ib1;
    tf2x32(0u, 42u, 0u, (uint32_t)b, ib0, ib1);
    uint32_t kw0, kw1, kB0, kB1;
    tf2x32(ib0, ib1, 0u, 0u, kw0, kw1);
    tf2x32(ib0, ib1, 0u, 1u, kB0, kB1);
    #pragma unroll
    for (int c = 0; c < 3; c++) {
        w[c]  = jnormal(kw0, kw1, (uint64_t)c) * 0.1f + 0.5f;
        bb[c] = jnormal(kB0, kB1, (uint64_t)c) * 0.01f;
    }
}

// ---------------------------------------------------------------------------
// Device scratch
// ---------------------------------------------------------------------------
struct Geo {
    float y0i, x0i, diagi, phi, cc, top, r, ca, sa, bright;
    uint32_t k2a, k2b;
    int valid;
    int pad;
};                                      // 14 words

#define NIMG_CHUNK 64
#define NPAT_CHUNK 8

__device__ Geo   g_geo[Bimg][Nbox];
__device__ float g_w[Bimg][3];
__device__ float g_bj[Bimg][3];
__device__ float g_isum[Bimg][NIMG_CHUNK];
__device__ float g_psum[Bimg][NPAT_CHUNK];

// ---------------------------------------------------------------------------
// K1 (k_prep): streaming copy+zero with fused image sums; patch sums; geometry.
// grid (64+8+1, 16), 256 thr.
// ---------------------------------------------------------------------------
__global__ void k_prep(const float* __restrict__ images,
                       const float* __restrict__ patch,
                       const float* __restrict__ boxes,
                       const float* __restrict__ scale_p,
                       float* __restrict__ oimg,
                       float* __restrict__ omask) {
    int b = blockIdx.y, g = blockIdx.x;

    if (g == NIMG_CHUNK + NPAT_CHUNK) {
        int n = threadIdx.x;
        if (n == 0) {
            float w[3], bb[3];
            wb_for(b, w, bb);
            #pragma unroll
            for (int c = 0; c < 3; c++) { g_w[b][c] = w[c]; g_bj[b][c] = bb[c]; }
        }
        if (n < Nbox) {
            float scale = scale_p[0];
            uint32_t ib0, ib1, kl0, kl1;
            tf2x32(0u, 42u, 0u, (uint32_t)b, ib0, ib1);
            tf2x32(ib0, ib1, 0u, 2u, kl0, kl1);
            uint32_t kn0, kn1;
            tf2x32(kl0, kl1, 0u, (uint32_t)n, kn0, kn1);
            uint32_t k10, k11, k20, k21, k30, k31;
            tf2x32(kn0, kn1, 0u, 0u, k10, k11);
            tf2x32(kn0, kn1, 0u, 1u, k20, k21);
            tf2x32(kn0, kn1, 0u, 2u, k30, k31);

            const float MAXA = (float)(20.0 * 3.14159265358979323846 / 180.0);
            float angle  = juniform(k10, k11, 0ull, -MAXA, MAXA);
            float bright = juniform(k30, k31, 0ull, -0.3f, 0.3f);

            const float* bx = boxes + ((size_t)b * Nbox + n) * 4;
            float ymin = bx[0], xmin = bx[1], ymax = bx[2], xmax = bx[3];
            float h  = ymax - ymin;
            float ww = xmax - xmin;
            float longer = fmaxf(h, ww);
            float ps   = floorf(longer * scale);
            float diag = fminf(sqrtf(2.0f) * ps, (float)Wim);
            float oy = ymin + h * 0.5f;
            float ox = xmin + ww * 0.5f;
            float y0 = fmaxf(oy - diag * 0.5f, 0.0f);
            float x0 = fmaxf(ox - diag * 0.5f, 0.0f);
            y0 = (y0 + diag > (float)Him) ? ((float)Him - diag) : y0;
            x0 = (x0 + diag > (float)Wim) ? ((float)Wim - diag) : x0;
            float phi   = fmaxf(floorf(ps), 1.0f);
            float diagi = floorf(diag);

            Geo gg;
            gg.y0i = floorf(y0); gg.x0i = floorf(x0);
            gg.diagi = diagi; gg.phi = phi;
            gg.cc  = (diagi - 1.0f) * 0.5f;
            gg.top = floorf((diagi - phi) * 0.5f);
            gg.r   = 300.0f / phi;
            gg.ca  = cosf(angle);
            gg.sa  = sinf(angle);
            gg.bright = bright;
            gg.k2a = k20; gg.k2b = k21;
            gg.valid = (phi * phi > 60.0f) ? 1 : 0;
            gg.pad = 0;
            g_geo[b][n] = gg;
        }
        return;
    }

    float acc = 0.0f;
    if (g < NIMG_CHUNK) {
        size_t base = (size_t)b * IMG + (size_t)g * (IMG / NIMG_CHUNK);
        const float4* src  = (const float4*)(images + base);
        float4* dimg = (float4*)(oimg + base);
        float4* dmsk = (float4*)(omask + base);
        const int nvec = (int)((IMG / NIMG_CHUNK) / 4);   // 4800 float4s
        const float4 z = make_float4(0.f, 0.f, 0.f, 0.f);
        float a0 = 0.f, a1 = 0.f, a2 = 0.f, a3 = 0.f;
        int i = threadIdx.x;
        // 4800 = 256*18.75; main loop 4x unrolled
        for (; i + 768 < nvec; i += 1024) {
            float4 v0 = __ldcs(src + i);
            float4 v1 = __ldcs(src + i + 256);
            float4 v2 = __ldcs(src + i + 512);
            float4 v3 = __ldcs(src + i + 768);
            __stcs(dimg + i,       v0); __stcs(dimg + i + 256, v1);
            __stcs(dimg + i + 512, v2); __stcs(dimg + i + 768, v3);
            __stcs(dmsk + i,       z);  __stcs(dmsk + i + 256, z);
            __stcs(dmsk + i + 512, z);  __stcs(dmsk + i + 768, z);
            a0 += (v0.x + v0.y) + (v0.z + v0.w);
            a1 += (v1.x + v1.y) + (v1.z + v1.w);
            a2 += (v2.x + v2.y) + (v2.z + v2.w);
            a3 += (v3.x + v3.y) + (v3.z + v3.w);
        }
        for (; i < nvec; i += 256) {
            float4 v = __ldcs(src + i);
            __stcs(dimg + i, v);
            __stcs(dmsk + i, z);
            a0 += (v.x + v.y) + (v.z + v.w);
        }
        acc = (a0 + a1) + (a2 + a3);
    } else {
        float w[3], bb[3];
        wb_for(b, w, bb);
        int gp = g - NIMG_CHUNK;
        int chunk = PTOT / NPAT_CHUNK;                    // 33750
        int base = gp * chunk;
        float a0 = 0.f, a1 = 0.f;
        int i = base + threadIdx.x;
        int end = base + chunk;
        for (; i + 256 < end; i += 512) {
            int c0 = i % 3;
            int c1 = (i + 256) % 3;
            a0 += fminf(fmaxf(w[c0] * patch[i] + bb[c0], -1.0f), 1.0f);
            a1 += fminf(fmaxf(w[c1] * patch[i + 256] + bb[c1], -1.0f), 1.0f);
        }
        if (i < end) {
            int c = i % 3;
            a0 += fminf(fmaxf(w[c] * patch[i] + bb[c], -1.0f), 1.0f);
        }
        acc = a0 + a1;
    }
    __shared__ float sh[256];
    sh[threadIdx.x] = acc;
    __syncthreads();
    for (int s = 128; s > 0; s >>= 1) {
        if (threadIdx.x < s) sh[threadIdx.x] += sh[threadIdx.x + s];
        __syncthreads();
    }
    if (threadIdx.x == 0) {
        if (g < NIMG_CHUNK) g_isum[b][g] = sh[0];
        else                g_psum[b][g - NIMG_CHUNK] = sh[0];
    }
}

// ---------------------------------------------------------------------------
// K2 (k_heavy): per-box tiles; pixel written iff this box is its LAST
// valid-src writer. grid (8, 8, 256), block (16, 16).
// Block-level convex rejection of tiles fully outside the valid region.
// ---------------------------------------------------------------------------
__global__ void k_heavy(const float* __restrict__ images,
                        const float* __restrict__ patch,
                        float* __restrict__ oimg,
                        float* __restrict__ omask) {
    int bz = blockIdx.z;
    int b = bz >> 4, n = bz & 15;

    // block-uniform rejects straight from global geo (L2-resident)
    const float* graw = (const float*)&g_geo[b][0];
    float diagi_n = graw[n * 14 + 2];
    int   valid_n = ((const int*)graw)[n * 14 + 12];
    int ty0 = blockIdx.y * 16, tx0 = blockIdx.x * 16;
    if (!valid_n || (float)ty0 >= diagi_n || (float)tx0 >= diagi_n) return;

    {
        // convex tile rejection: py/px linear in (u,v); test 4 tile corners
        float cc  = graw[n * 14 + 4];
        float top = graw[n * 14 + 5];
        float ca  = graw[n * 14 + 7];
        float sa  = graw[n * 14 + 8];
        float phi = graw[n * 14 + 3];
        float lim = phi - 1.0f;
        float u0 = (float)ty0 - cc, u1 = (float)(ty0 + 15) - cc;
        float v0 = (float)tx0 - cc, v1 = (float)(tx0 + 15) - cc;
        float bias = cc - top;
        // py = bias + ca*u - sa*v ; px = bias + sa*u + ca*v  (ca > 0 always)
        float pyA = bias + ca * u0 - sa * v0, pyB = bias + ca * u0 - sa * v1;
        float pyC = bias + ca * u1 - sa * v0, pyD = bias + ca * u1 - sa * v1;
        float pxA = bias + sa * u0 + ca * v0, pxB = bias + sa * u0 + ca * v1;
        float pxC = bias + sa * u1 + ca * v0, pxD = bias + sa * u1 + ca * v1;
        float pymin = fminf(fminf(pyA, pyB), fminf(pyC, pyD));
        float pymax = fmaxf(fmaxf(pyA, pyB), fmaxf(pyC, pyD));
        float pxmin = fminf(fminf(pxA, pxB), fminf(pxC, pxD));
        float pxmax = fmaxf(fmaxf(pxA, pxB), fmaxf(pxC, pxD));
        if (pymax < 0.0f || pymin > lim || pxmax < 0.0f || pxmin > lim) return;
    }

    __shared__ Geo   sg[Nbox];
    __shared__ float s_s;
    int t = threadIdx.y * 16 + threadIdx.x;
    if (t < Nbox * 14)
        ((float*)sg)[t] = graw[t];
    if (t >= 224 && t < 256) {          // warp 7: brightness scalar
        int l = t - 224;
        float si = g_isum[b][l] + g_isum[b][l + 32];
        float sp = (l < NPAT_CHUNK) ? g_psum[b][l] : 0.0f;
        #pragma unroll
        for (int o = 16; o > 0; o >>= 1) {
            si += __shfl_down_sync(0xffffffffu, si, o);
            sp += __shfl_down_sync(0xffffffffu, sp, o);
        }
        if (l == 0) s_s = si / 1228800.0f - sp / 270000.0f;
    }
    __syncthreads();

    Geo G = sg[n];
    // block-uniform mask of LATER boxes overlapping this tile
    float aty0 = G.y0i + (float)ty0;
    float atx0 = G.x0i + (float)tx0;
    unsigned mj = 0;
    for (int j = n + 1; j < Nbox; j++) {
        const Geo& J = sg[j];
        if (J.valid &&
            aty0 + 16.0f > J.y0i && aty0 < J.y0i + J.diagi &&
            atx0 + 16.0f > J.x0i && atx0 < J.x0i + J.diagi)
            mj |= 1u << j;
    }

    int u = ty0 + threadIdx.y;
    int v = tx0 + threadIdx.x;
    float uf = (float)u, vf = (float)v;
    if (uf >= G.diagi || vf >= G.diagi) return;

    // valid_src for box n
    float um = uf - G.cc, vm = vf - G.cc;
    float py = G.cc + G.ca * um - G.sa * vm - G.top;
    float px = G.cc + G.sa * um + G.ca * vm - G.top;
    float lim = G.phi - 1.0f;
    if (!(py >= 0.0f && py <= lim && px >= 0.0f && px <= lim)) return;

    // skip if any LATER box also writes this pixel
    float yab = G.y0i + uf, xab = G.x0i + vf;
    unsigned mm = mj;
    while (mm) {
        int j = __ffs(mm) - 1;
        mm &= mm - 1;
        const Geo& J = sg[j];
        float uj = yab - J.y0i, vj = xab - J.x0i;
        if (uj >= 0.f && vj >= 0.f && uj < J.diagi && vj < J.diagi) {
            float umj = uj - J.cc, vmj = vj - J.cc;
            float pyj = J.cc + J.ca * umj - J.sa * vmj - J.top;
            float pxj = J.cc + J.sa * umj + J.ca * vmj - J.top;
            float lj = J.phi - 1.0f;
            if (pyj >= 0.f && pyj <= lj && pxj >= 0.f && pxj <= lj) return;
        }
    }

    // this box is the final writer: bilinear sample + jitter + noise
    int y = (int)G.y0i + u;
    int x = (int)G.x0i + v;

    float sy = (py + 0.5f) * G.r - 0.5f;
    float sx = (px + 0.5f) * G.r - 0.5f;
    float fy = floorf(sy), fx = floorf(sx);
    float wy = sy - fy, wx = sx - fx;
    int y0c = min(max((int)fy, 0), PHp - 1);
    int y1c = min(y0c + 1, PHp - 1);
    int x0c = min(max((int)fx, 0), PWp - 1);
    int x1c = min(x0c + 1, PWp - 1);
    int o00 = (y0c * PWp + x0c) * 3;
    int o01 = (y0c * PWp + x1c) * 3;
    int o10 = (y1c * PWp + x0c) * 3;
    int o11 = (y1c * PWp + x1c) * 3;

    uint32_t nb = ((uint32_t)y * (uint32_t)Wim + (uint32_t)x) * 3u;
    uint32_t bits[3];
    tf3(G.k2a, G.k2b, nb, bits);

    float s = s_s;
    float omy = 1.0f - wy, omx = 1.0f - wx;
    float w00 = omy * omx, w01 = omy * wx, w10 = wy * omx, w11 = wy * wx;
    size_t base = (((size_t)b * Him + y) * Wim + x) * 3;
    float res[3];
    #pragma unroll
    for (int c = 0; c < 3; c++) {
        float wc = g_w[b][c], bc = g_bj[b][c];
#define ADJ(pp) fminf(fmaxf(fminf(fmaxf(fmaf(wc, (pp), bc), -1.f), 1.f) + s, -1.f), 1.f)
        float samp = ADJ(patch[o00 + c]) * w00 + ADJ(patch[o01 + c]) * w01
                   + ADJ(patch[o10 + c]) * w10 + ADJ(patch[o11 + c]) * w11;
#undef ADJ
        float noise = fmaxf(-0.1f, fmaf(bits_to_unit(bits[c]), 0.2f, -0.1f));
        res[c] = fminf(fmaxf(samp + noise + G.bright, -1.0f), 1.0f);
    }

    float i0 = images[base], i1 = images[base + 1], i2 = images[base + 2];
    oimg[base]      = res[0]; oimg[base + 1]  = res[1]; oimg[base + 2]  = res[2];
    omask[base]     = i0 - res[0];
    omask[base + 1] = i1 - res[1];
    omask[base + 2] = i2 - res[2];
}

// ---------------------------------------------------------------------------
extern "C" void kernel_launch(void* const* d_in, const int* in_sizes, int n_in,
                              void* d_out, int out_size) {
    const float* boxes  = (const float*)d_in[0];
    const float* images = (const float*)d_in[1];
    const float* patch  = (const float*)d_in[2];
    const float* scale  = (const float*)d_in[3];
    float* out   = (float*)d_out;
    float* omask = out + (size_t)Bimg * IMG;

    k_prep<<<dim3(NIMG_CHUNK + NPAT_CHUNK + 1, 16), 256>>>(
        images, patch, boxes, scale, out, omask);
    k_heavy<<<dim3(8, 8, Bimg * Nbox), dim3(16, 16)>>>(
        images, patch, out, omask);

    (void)in_sizes; (void)n_in; (void)out_size;
}

// round 9
// speedup vs baseline: 1.4221x; 1.0049x over previous
#include <cuda_runtime.h>
#include <stdint.h>
#include <math.h>

#define Bimg 16
#define Nbox 16
#define Him  640
#define Wim  640
#define PHp  300
#define PWp  300
#define PTOT (PHp*PWp*3)
#define IMG  ((size_t)Him * Wim * 3)

// ---------------------------------------------------------------------------
// JAX threefry2x32 (20 rounds), partitionable random-bits convention
// ---------------------------------------------------------------------------
__device__ __forceinline__ void tf2x32(uint32_t k0, uint32_t k1,
                                       uint32_t x0, uint32_t x1,
                                       uint32_t& o0, uint32_t& o1) {
    uint32_t ks2 = k0 ^ k1 ^ 0x1BD11BDAu;
    x0 += k0; x1 += k1;
#define TF_RND(r) { x0 += x1; x1 = __funnelshift_l(x1, x1, (r)); x1 ^= x0; }
    TF_RND(13) TF_RND(15) TF_RND(26) TF_RND(6)
    x0 += k1;  x1 += ks2 + 1u;
    TF_RND(17) TF_RND(29) TF_RND(16) TF_RND(24)
    x0 += ks2; x1 += k0 + 2u;
    TF_RND(13) TF_RND(15) TF_RND(26) TF_RND(6)
    x0 += k0;  x1 += k1 + 3u;
    TF_RND(17) TF_RND(29) TF_RND(16) TF_RND(24)
    x0 += k1;  x1 += ks2 + 4u;
    TF_RND(13) TF_RND(15) TF_RND(26) TF_RND(6)
    x0 += ks2; x1 += k0 + 5u;
#undef TF_RND
    o0 = x0; o1 = x1;
}

__device__ __forceinline__ uint32_t rbits(uint32_t k0, uint32_t k1, uint64_t idx) {
    uint32_t a, b;
    tf2x32(k0, k1, (uint32_t)(idx >> 32), (uint32_t)idx, a, b);
    return a ^ b;
}

// 3 interleaved threefry chains, counters (c0, c0+1, c0+2), hi word = 0.
__device__ __forceinline__ void tf3(uint32_t k0, uint32_t k1, uint32_t c0,
                                    uint32_t out[3]) {
    uint32_t ks2 = k0 ^ k1 ^ 0x1BD11BDAu;
    uint32_t a0 = k0, a1 = k0, a2 = k0;
    uint32_t b0 = c0 + k1, b1 = c0 + 1u + k1, b2 = c0 + 2u + k1;
#define R3(r)  { a0 += b0; b0 = __funnelshift_l(b0,b0,(r)); b0 ^= a0; \
                 a1 += b1; b1 = __funnelshift_l(b1,b1,(r)); b1 ^= a1; \
                 a2 += b2; b2 = __funnelshift_l(b2,b2,(r)); b2 ^= a2; }
#define INJ3(ka, kb) { a0 += (ka); b0 += (kb); a1 += (ka); b1 += (kb); a2 += (ka); b2 += (kb); }
    R3(13) R3(15) R3(26) R3(6)
    INJ3(k1, ks2 + 1u)
    R3(17) R3(29) R3(16) R3(24)
    INJ3(ks2, k0 + 2u)
    R3(13) R3(15) R3(26) R3(6)
    INJ3(k0, k1 + 3u)
    R3(17) R3(29) R3(16) R3(24)
    INJ3(k1, ks2 + 4u)
    R3(13) R3(15) R3(26) R3(6)
    out[0] = (a0 + ks2) ^ (b0 + k0 + 5u);
    out[1] = (a1 + ks2) ^ (b1 + k0 + 5u);
    out[2] = (a2 + ks2) ^ (b2 + k0 + 5u);
#undef R3
#undef INJ3
}

__device__ __forceinline__ float bits_to_unit(uint32_t bits) {
    return __uint_as_float((bits >> 9) | 0x3f800000u) - 1.0f;
}

__device__ __forceinline__ float juniform(uint32_t k0, uint32_t k1, uint64_t i,
                                          float lo, float hi) {
    float f = bits_to_unit(rbits(k0, k1, i));
    return fmaxf(lo, f * (hi - lo) + lo);
}

__device__ __forceinline__ float erfinv_xla(float x) {
    float w = -log1pf(-x * x);
    float p;
    if (w < 5.0f) {
        w -= 2.5f;
        p = 2.81022636e-08f;
        p = fmaf(p, w, 3.43273939e-07f);
        p = fmaf(p, w, -3.5233877e-06f);
        p = fmaf(p, w, -4.39150654e-06f);
        p = fmaf(p, w, 0.00021858087f);
        p = fmaf(p, w, -0.00125372503f);
        p = fmaf(p, w, -0.00417768164f);
        p = fmaf(p, w, 0.246640727f);
        p = fmaf(p, w, 1.50140941f);
    } else {
        w = sqrtf(w) - 3.0f;
        p = -0.000200214257f;
        p = fmaf(p, w, 0.000100950558f);
        p = fmaf(p, w, 0.00134934322f);
        p = fmaf(p, w, -0.00367342844f);
        p = fmaf(p, w, 0.00573950773f);
        p = fmaf(p, w, -0.0076224613f);
        p = fmaf(p, w, 0.00943887047f);
        p = fmaf(p, w, 1.00167406f);
        p = fmaf(p, w, 2.83297682f);
    }
    return p * x;
}

__device__ __forceinline__ float jnormal(uint32_t k0, uint32_t k1, uint64_t i) {
    const float lo = -0.99999994f;
    float u = juniform(k0, k1, i, lo, 1.0f);
    return 1.41421354f * erfinv_xla(u);
}

__device__ __forceinline__ void wb_for(int b, float w[3], float bb[3]) {
    uint32_t ib0, ib1;
    tf2x32(0u, 42u, 0u, (uint32_t)b, ib0, ib1);
    uint32_t kw0, kw1, kB0, kB1;
    tf2x32(ib0, ib1, 0u, 0u, kw0, kw1);
    tf2x32(ib0, ib1, 0u, 1u, kB0, kB1);
    #pragma unroll
    for (int c = 0; c < 3; c++) {
        w[c]  = jnormal(kw0, kw1, (uint64_t)c) * 0.1f + 0.5f;
        bb[c] = jnormal(kB0, kB1, (uint64_t)c) * 0.01f;
    }
}

// ---------------------------------------------------------------------------
// Device scratch
// ---------------------------------------------------------------------------
struct Geo {
    float y0i, x0i, diagi, phi, cc, top, r, ca, sa, bright;
    uint32_t k2a, k2b;
    int valid;
    int pad;
};                                      // 14 words

#define NIMG_CHUNK 128
#define NPAT_CHUNK 8

__device__ Geo      g_geo[Bimg][Nbox];
__device__ float    g_w[Bimg][3];
__device__ float    g_bj[Bimg][3];
__device__ float    g_isum[Bimg][NIMG_CHUNK];
__device__ float    g_psum[Bimg][NPAT_CHUNK];
__device__ float    g_s[Bimg];
__device__ unsigned g_later[Bimg][Nbox];

// ---------------------------------------------------------------------------
// K1 (k_prep): streaming copy+zero with fused image sums; patch sums;
// geometry + later-writer masks. grid (128+8+1, 16), 256 thr.
// ---------------------------------------------------------------------------
__global__ void k_prep(const float* __restrict__ images,
                       const float* __restrict__ patch,
                       const float* __restrict__ boxes,
                       const float* __restrict__ scale_p,
                       float* __restrict__ oimg,
                       float* __restrict__ omask) {
    int b = blockIdx.y, g = blockIdx.x;

    if (g == NIMG_CHUNK + NPAT_CHUNK) {
        __shared__ Geo sgeo[Nbox];
        int n = threadIdx.x;
        if (n == 0) {
            float w[3], bb[3];
            wb_for(b, w, bb);
            #pragma unroll
            for (int c = 0; c < 3; c++) { g_w[b][c] = w[c]; g_bj[b][c] = bb[c]; }
        }
        if (n < Nbox) {
            float scale = scale_p[0];
            uint32_t ib0, ib1, kl0, kl1;
            tf2x32(0u, 42u, 0u, (uint32_t)b, ib0, ib1);
            tf2x32(ib0, ib1, 0u, 2u, kl0, kl1);
            uint32_t kn0, kn1;
            tf2x32(kl0, kl1, 0u, (uint32_t)n, kn0, kn1);
            uint32_t k10, k11, k20, k21, k30, k31;
            tf2x32(kn0, kn1, 0u, 0u, k10, k11);
            tf2x32(kn0, kn1, 0u, 1u, k20, k21);
            tf2x32(kn0, kn1, 0u, 2u, k30, k31);

            const float MAXA = (float)(20.0 * 3.14159265358979323846 / 180.0);
            float angle  = juniform(k10, k11, 0ull, -MAXA, MAXA);
            float bright = juniform(k30, k31, 0ull, -0.3f, 0.3f);

            const float* bx = boxes + ((size_t)b * Nbox + n) * 4;
            float ymin = bx[0], xmin = bx[1], ymax = bx[2], xmax = bx[3];
            float h  = ymax - ymin;
            float ww = xmax - xmin;
            float longer = fmaxf(h, ww);
            float ps   = floorf(longer * scale);
            float diag = fminf(sqrtf(2.0f) * ps, (float)Wim);
            float oy = ymin + h * 0.5f;
            float ox = xmin + ww * 0.5f;
            float y0 = fmaxf(oy - diag * 0.5f, 0.0f);
            float x0 = fmaxf(ox - diag * 0.5f, 0.0f);
            y0 = (y0 + diag > (float)Him) ? ((float)Him - diag) : y0;
            x0 = (x0 + diag > (float)Wim) ? ((float)Wim - diag) : x0;
            float phi   = fmaxf(floorf(ps), 1.0f);
            float diagi = floorf(diag);

            Geo gg;
            gg.y0i = floorf(y0); gg.x0i = floorf(x0);
            gg.diagi = diagi; gg.phi = phi;
            gg.cc  = (diagi - 1.0f) * 0.5f;
            gg.top = floorf((diagi - phi) * 0.5f);
            gg.r   = 300.0f / phi;
            gg.ca  = cosf(angle);
            gg.sa  = sinf(angle);
            gg.bright = bright;
            gg.k2a = k20; gg.k2b = k21;
            gg.valid = (phi * phi > 60.0f) ? 1 : 0;
            gg.pad = 0;
            g_geo[b][n] = gg;
            sgeo[n] = gg;
        }
        __syncthreads();
        if (n < Nbox) {
            // box-level later-writer candidate mask
            const Geo& N = sgeo[n];
            unsigned m = 0;
            for (int j = n + 1; j < Nbox; j++) {
                const Geo& J = sgeo[j];
                if (J.valid &&
                    N.y0i < J.y0i + J.diagi && N.y0i + N.diagi > J.y0i &&
                    N.x0i < J.x0i + J.diagi && N.x0i + N.diagi > J.x0i)
                    m |= 1u << j;
            }
            g_later[b][n] = m;
        }
        return;
    }

    float acc = 0.0f;
    if (g < NIMG_CHUNK) {
        size_t base = (size_t)b * IMG + (size_t)g * (IMG / NIMG_CHUNK);
        const float4* src  = (const float4*)(images + base);
        float4* dimg = (float4*)(oimg + base);
        float4* dmsk = (float4*)(omask + base);
        const int nvec = (int)((IMG / NIMG_CHUNK) / 4);   // 2400 float4s
        const float4 z = make_float4(0.f, 0.f, 0.f, 0.f);
        float a0 = 0.f, a1 = 0.f, a2 = 0.f, a3 = 0.f;
        int i = threadIdx.x;
        for (; i + 768 < nvec; i += 1024) {
            float4 v0 = __ldcs(src + i);
            float4 v1 = __ldcs(src + i + 256);
            float4 v2 = __ldcs(src + i + 512);
            float4 v3 = __ldcs(src + i + 768);
            __stcs(dimg + i,       v0); __stcs(dimg + i + 256, v1);
            __stcs(dimg + i + 512, v2); __stcs(dimg + i + 768, v3);
            __stcs(dmsk + i,       z);  __stcs(dmsk + i + 256, z);
            __stcs(dmsk + i + 512, z);  __stcs(dmsk + i + 768, z);
            a0 += (v0.x + v0.y) + (v0.z + v0.w);
            a1 += (v1.x + v1.y) + (v1.z + v1.w);
            a2 += (v2.x + v2.y) + (v2.z + v2.w);
            a3 += (v3.x + v3.y) + (v3.z + v3.w);
        }
        for (; i < nvec; i += 256) {
            float4 v = __ldcs(src + i);
            __stcs(dimg + i, v);
            __stcs(dmsk + i, z);
            a0 += (v.x + v.y) + (v.z + v.w);
        }
        acc = (a0 + a1) + (a2 + a3);
    } else {
        float w[3], bb[3];
        wb_for(b, w, bb);
        int gp = g - NIMG_CHUNK;
        int chunk = PTOT / NPAT_CHUNK;                    // 33750
        int base = gp * chunk;
        float a0 = 0.f, a1 = 0.f;
        int i = base + threadIdx.x;
        int end = base + chunk;
        for (; i + 256 < end; i += 512) {
            int c0 = i % 3;
            int c1 = (i + 256) % 3;
            a0 += fminf(fmaxf(w[c0] * patch[i] + bb[c0], -1.0f), 1.0f);
            a1 += fminf(fmaxf(w[c1] * patch[i + 256] + bb[c1], -1.0f), 1.0f);
        }
        if (i < end) {
            int c = i % 3;
            a0 += fminf(fmaxf(w[c] * patch[i] + bb[c], -1.0f), 1.0f);
        }
        acc = a0 + a1;
    }
    __shared__ float sh[256];
    sh[threadIdx.x] = acc;
    __syncthreads();
    for (int s = 128; s > 0; s >>= 1) {
        if (threadIdx.x < s) sh[threadIdx.x] += sh[threadIdx.x + s];
        __syncthreads();
    }
    if (threadIdx.x == 0) {
        if (g < NIMG_CHUNK) g_isum[b][g] = sh[0];
        else                g_psum[b][g - NIMG_CHUNK] = sh[0];
    }
}

// ---------------------------------------------------------------------------
// K2 (k_s): finalize per-image brightness shift. grid (16), 32 thr.
// ---------------------------------------------------------------------------
__global__ void k_s() {
    int b = blockIdx.x;
    int l = threadIdx.x;
    float si = g_isum[b][l] + g_isum[b][l + 32]
             + g_isum[b][l + 64] + g_isum[b][l + 96];
    float sp = (l < NPAT_CHUNK) ? g_psum[b][l] : 0.0f;
    #pragma unroll
    for (int o = 16; o > 0; o >>= 1) {
        si += __shfl_down_sync(0xffffffffu, si, o);
        sp += __shfl_down_sync(0xffffffffu, sp, o);
    }
    if (l == 0) g_s[b] = si / 1228800.0f - sp / 270000.0f;
}

// ---------------------------------------------------------------------------
// K3 (k_heavy): per-box tiles; pixel written iff this box is its LAST
// valid-src writer. grid (8, 8, 256), block (16, 16).
// Barrier-free, smem-free: all shared state precomputed.
// ---------------------------------------------------------------------------
__global__ void k_heavy(const float* __restrict__ images,
                        const float* __restrict__ patch,
                        float* __restrict__ oimg,
                        float* __restrict__ omask) {
    int bz = blockIdx.z;
    int b = bz >> 4, n = bz & 15;

    const Geo G = g_geo[b][n];          // uniform broadcast loads
    if (!G.valid) return;
    int ty0 = blockIdx.y * 16, tx0 = blockIdx.x * 16;
    if ((float)ty0 >= G.diagi || (float)tx0 >= G.diagi) return;

    {
        // convex tile rejection: py/px linear in (u,v); test 4 corners
        float lim = G.phi - 1.0f;
        float u0 = (float)ty0 - G.cc, u1 = (float)(ty0 + 15) - G.cc;
        float v0 = (float)tx0 - G.cc, v1 = (float)(tx0 + 15) - G.cc;
        float bias = G.cc - G.top;
        float pyA = bias + G.ca * u0 - G.sa * v0, pyB = bias + G.ca * u0 - G.sa * v1;
        float pyC = bias + G.ca * u1 - G.sa * v0, pyD = bias + G.ca * u1 - G.sa * v1;
        float pxA = bias + G.sa * u0 + G.ca * v0, pxB = bias + G.sa * u0 + G.ca * v1;
        float pxC = bias + G.sa * u1 + G.ca * v0, pxD = bias + G.sa * u1 + G.ca * v1;
        float pymin = fminf(fminf(pyA, pyB), fminf(pyC, pyD));
        float pymax = fmaxf(fmaxf(pyA, pyB), fmaxf(pyC, pyD));
        float pxmin = fminf(fminf(pxA, pxB), fminf(pxC, pxD));
        float pxmax = fmaxf(fmaxf(pxA, pxB), fmaxf(pxC, pxD));
        if (pymax < 0.0f || pymin > lim || pxmax < 0.0f || pxmin > lim) return;
    }

    int u = ty0 + threadIdx.y;
    int v = tx0 + threadIdx.x;
    float uf = (float)u, vf = (float)v;
    if (uf >= G.diagi || vf >= G.diagi) return;

    // valid_src for box n
    float um = uf - G.cc, vm = vf - G.cc;
    float py = G.cc + G.ca * um - G.sa * vm - G.top;
    float px = G.cc + G.sa * um + G.ca * vm - G.top;
    float lim = G.phi - 1.0f;
    if (!(py >= 0.0f && py <= lim && px >= 0.0f && px <= lim)) return;

    // skip if any LATER box also writes this pixel (box-level candidates)
    {
        float yab = G.y0i + uf, xab = G.x0i + vf;
        unsigned mm = g_later[b][n];
        while (mm) {
            int j = __ffs(mm) - 1;
            mm &= mm - 1;
            const Geo J = g_geo[b][j];
            float uj = yab - J.y0i, vj = xab - J.x0i;
            if (uj >= 0.f && vj >= 0.f && uj < J.diagi && vj < J.diagi) {
                float umj = uj - J.cc, vmj = vj - J.cc;
                float pyj = J.cc + J.ca * umj - J.sa * vmj - J.top;
                float pxj = J.cc + J.sa * umj + J.ca * vmj - J.top;
                float lj = J.phi - 1.0f;
                if (pyj >= 0.f && pyj <= lj && pxj >= 0.f && pxj <= lj) return;
            }
        }
    }

    // this box is the final writer: bilinear sample + jitter + noise
    int y = (int)G.y0i + u;
    int x = (int)G.x0i + v;

    float sy = (py + 0.5f) * G.r - 0.5f;
    float sx = (px + 0.5f) * G.r - 0.5f;
    float fy = floorf(sy), fx = floorf(sx);
    float wy = sy - fy, wx = sx - fx;
    int y0c = min(max((int)fy, 0), PHp - 1);
    int y1c = min(y0c + 1, PHp - 1);
    int x0c = min(max((int)fx, 0), PWp - 1);
    int x1c = min(x0c + 1, PWp - 1);
    int o00 = (y0c * PWp + x0c) * 3;
    int o01 = (y0c * PWp + x1c) * 3;
    int o10 = (y1c * PWp + x0c) * 3;
    int o11 = (y1c * PWp + x1c) * 3;

    uint32_t nb = ((uint32_t)y * (uint32_t)Wim + (uint32_t)x) * 3u;
    uint32_t bits[3];
    tf3(G.k2a, G.k2b, nb, bits);

    float s = g_s[b];
    float omy = 1.0f - wy, omx = 1.0f - wx;
    float w00 = omy * omx, w01 = omy * wx, w10 = wy * omx, w11 = wy * wx;
    size_t base = (((size_t)b * Him + y) * Wim + x) * 3;
    float res[3];
    #pragma unroll
    for (int c = 0; c < 3; c++) {
        float wc = g_w[b][c], bc = g_bj[b][c];
#define ADJ(pp) fminf(fmaxf(fminf(fmaxf(fmaf(wc, (pp), bc), -1.f), 1.f) + s, -1.f), 1.f)
        float samp = ADJ(patch[o00 + c]) * w00 + ADJ(patch[o01 + c]) * w01
                   + ADJ(patch[o10 + c]) * w10 + ADJ(patch[o11 + c]) * w11;
#undef ADJ
        float noise = fmaxf(-0.1f, fmaf(bits_to_unit(bits[c]), 0.2f, -0.1f));
        res[c] = fminf(fmaxf(samp + noise + G.bright, -1.0f), 1.0f);
    }

    float i0 = images[base], i1 = images[base + 1], i2 = images[base + 2];
    oimg[base]      = res[0]; oimg[base + 1]  = res[1]; oimg[base + 2]  = res[2];
    omask[base]     = i0 - res[0];
    omask[base + 1] = i1 - res[1];
    omask[base + 2] = i2 - res[2];
}

// ---------------------------------------------------------------------------
extern "C" void kernel_launch(void* const* d_in, const int* in_sizes, int n_in,
                              void* d_out, int out_size) {
    const float* boxes  = (const float*)d_in[0];
    const float* images = (const float*)d_in[1];
    const float* patch  = (const float*)d_in[2];
    const float* scale  = (const float*)d_in[3];
    float* out   = (float*)d_out;
    float* omask = out + (size_t)Bimg * IMG;

    k_prep<<<dim3(NIMG_CHUNK + NPAT_CHUNK + 1, 16), 256>>>(
        images, patch, boxes, scale, out, omask);
    k_s<<<16, 32>>>();
    k_heavy<<<dim3(8, 8, Bimg * Nbox), dim3(16, 16)>>>(
        images, patch, out, omask);

    (void)in_sizes; (void)n_in; (void)out_size;
}

// round 10
// speedup vs baseline: 1.5331x; 1.0781x over previous
#include <cuda_runtime.h>
#include <stdint.h>
#include <math.h>

#define Bimg 16
#define Nbox 16
#define Him  640
#define Wim  640
#define PHp  300
#define PWp  300
#define PTOT (PHp*PWp*3)
#define IMG  ((size_t)Him * Wim * 3)

// ---------------------------------------------------------------------------
// JAX threefry2x32 (20 rounds), partitionable random-bits convention
// ---------------------------------------------------------------------------
__device__ __forceinline__ void tf2x32(uint32_t k0, uint32_t k1,
                                       uint32_t x0, uint32_t x1,
                                       uint32_t& o0, uint32_t& o1) {
    uint32_t ks2 = k0 ^ k1 ^ 0x1BD11BDAu;
    x0 += k0; x1 += k1;
#define TF_RND(r) { x0 += x1; x1 = __funnelshift_l(x1, x1, (r)); x1 ^= x0; }
    TF_RND(13) TF_RND(15) TF_RND(26) TF_RND(6)
    x0 += k1;  x1 += ks2 + 1u;
    TF_RND(17) TF_RND(29) TF_RND(16) TF_RND(24)
    x0 += ks2; x1 += k0 + 2u;
    TF_RND(13) TF_RND(15) TF_RND(26) TF_RND(6)
    x0 += k0;  x1 += k1 + 3u;
    TF_RND(17) TF_RND(29) TF_RND(16) TF_RND(24)
    x0 += k1;  x1 += ks2 + 4u;
    TF_RND(13) TF_RND(15) TF_RND(26) TF_RND(6)
    x0 += ks2; x1 += k0 + 5u;
#undef TF_RND
    o0 = x0; o1 = x1;
}

__device__ __forceinline__ uint32_t rbits(uint32_t k0, uint32_t k1, uint64_t idx) {
    uint32_t a, b;
    tf2x32(k0, k1, (uint32_t)(idx >> 32), (uint32_t)idx, a, b);
    return a ^ b;
}

// 3 interleaved threefry chains, counters (c0, c0+1, c0+2), hi word = 0.
__device__ __forceinline__ void tf3(uint32_t k0, uint32_t k1, uint32_t c0,
                                    uint32_t out[3]) {
    uint32_t ks2 = k0 ^ k1 ^ 0x1BD11BDAu;
    uint32_t a0 = k0, a1 = k0, a2 = k0;
    uint32_t b0 = c0 + k1, b1 = c0 + 1u + k1, b2 = c0 + 2u + k1;
#define R3(r)  { a0 += b0; b0 = __funnelshift_l(b0,b0,(r)); b0 ^= a0; \
                 a1 += b1; b1 = __funnelshift_l(b1,b1,(r)); b1 ^= a1; \
                 a2 += b2; b2 = __funnelshift_l(b2,b2,(r)); b2 ^= a2; }
#define INJ3(ka, kb) { a0 += (ka); b0 += (kb); a1 += (ka); b1 += (kb); a2 += (ka); b2 += (kb); }
    R3(13) R3(15) R3(26) R3(6)
    INJ3(k1, ks2 + 1u)
    R3(17) R3(29) R3(16) R3(24)
    INJ3(ks2, k0 + 2u)
    R3(13) R3(15) R3(26) R3(6)
    INJ3(k0, k1 + 3u)
    R3(17) R3(29) R3(16) R3(24)
    INJ3(k1, ks2 + 4u)
    R3(13) R3(15) R3(26) R3(6)
    out[0] = (a0 + ks2) ^ (b0 + k0 + 5u);
    out[1] = (a1 + ks2) ^ (b1 + k0 + 5u);
    out[2] = (a2 + ks2) ^ (b2 + k0 + 5u);
#undef R3
#undef INJ3
}

__device__ __forceinline__ float bits_to_unit(uint32_t bits) {
    return __uint_as_float((bits >> 9) | 0x3f800000u) - 1.0f;
}

__device__ __forceinline__ float juniform(uint32_t k0, uint32_t k1, uint64_t i,
                                          float lo, float hi) {
    float f = bits_to_unit(rbits(k0, k1, i));
    return fmaxf(lo, f * (hi - lo) + lo);
}

__device__ __forceinline__ float erfinv_xla(float x) {
    float w = -log1pf(-x * x);
    float p;
    if (w < 5.0f) {
        w -= 2.5f;
        p = 2.81022636e-08f;
        p = fmaf(p, w, 3.43273939e-07f);
        p = fmaf(p, w, -3.5233877e-06f);
        p = fmaf(p, w, -4.39150654e-06f);
        p = fmaf(p, w, 0.00021858087f);
        p = fmaf(p, w, -0.00125372503f);
        p = fmaf(p, w, -0.00417768164f);
        p = fmaf(p, w, 0.246640727f);
        p = fmaf(p, w, 1.50140941f);
    } else {
        w = sqrtf(w) - 3.0f;
        p = -0.000200214257f;
        p = fmaf(p, w, 0.000100950558f);
        p = fmaf(p, w, 0.00134934322f);
        p = fmaf(p, w, -0.00367342844f);
        p = fmaf(p, w, 0.00573950773f);
        p = fmaf(p, w, -0.0076224613f);
        p = fmaf(p, w, 0.00943887047f);
        p = fmaf(p, w, 1.00167406f);
        p = fmaf(p, w, 2.83297682f);
    }
    return p * x;
}

__device__ __forceinline__ float jnormal(uint32_t k0, uint32_t k1, uint64_t i) {
    const float lo = -0.99999994f;
    float u = juniform(k0, k1, i, lo, 1.0f);
    return 1.41421354f * erfinv_xla(u);
}

__device__ __forceinline__ void wb_for(int b, float w[3], float bb[3]) {
    uint32_t ib0, ib1;
    tf2x32(0u, 42u, 0u, (uint32_t)b, ib0, ib1);
    uint32_t kw0, kw1, kB0, kB1;
    tf2x32(ib0, ib1, 0u, 0u, kw0, kw1);
    tf2x32(ib0, ib1, 0u, 1u, kB0, kB1);
    #pragma unroll
    for (int c = 0; c < 3; c++) {
        w[c]  = jnormal(kw0, kw1, (uint64_t)c) * 0.1f + 0.5f;
        bb[c] = jnormal(kB0, kB1, (uint64_t)c) * 0.01f;
    }
}

// ---------------------------------------------------------------------------
// Device scratch
// ---------------------------------------------------------------------------
struct Geo {
    float y0i, x0i, diagi, phi, cc, top, r, ca, sa, bright;
    uint32_t k2a, k2b;
    int valid;
    int pad;
};                                      // 14 words

#define NIMG_CHUNK 128
#define NPAT_CHUNK 8

__device__ Geo      g_geo[Bimg][Nbox];
__device__ float    g_w[Bimg][3];
__device__ float    g_bj[Bimg][3];
__device__ float    g_isum[Bimg][NIMG_CHUNK];
__device__ float    g_psum[Bimg][NPAT_CHUNK];
__device__ float    g_s[Bimg];
__device__ unsigned g_later[Bimg][Nbox];

// ---------------------------------------------------------------------------
// K1 (k_prep): streaming copy+zero with fused image sums; patch sums;
// geometry + later-writer masks. grid (128+8+1, 16), 256 thr.
// ---------------------------------------------------------------------------
__global__ void k_prep(const float* __restrict__ images,
                       const float* __restrict__ patch,
                       const float* __restrict__ boxes,
                       const float* __restrict__ scale_p,
                       float* __restrict__ oimg,
                       float* __restrict__ omask) {
    int b = blockIdx.y, g = blockIdx.x;

    if (g == NIMG_CHUNK + NPAT_CHUNK) {
        __shared__ Geo sgeo[Nbox];
        int n = threadIdx.x;
        if (n == 0) {
            float w[3], bb[3];
            wb_for(b, w, bb);
            #pragma unroll
            for (int c = 0; c < 3; c++) { g_w[b][c] = w[c]; g_bj[b][c] = bb[c]; }
        }
        if (n < Nbox) {
            float scale = scale_p[0];
            uint32_t ib0, ib1, kl0, kl1;
            tf2x32(0u, 42u, 0u, (uint32_t)b, ib0, ib1);
            tf2x32(ib0, ib1, 0u, 2u, kl0, kl1);
            uint32_t kn0, kn1;
            tf2x32(kl0, kl1, 0u, (uint32_t)n, kn0, kn1);
            uint32_t k10, k11, k20, k21, k30, k31;
            tf2x32(kn0, kn1, 0u, 0u, k10, k11);
            tf2x32(kn0, kn1, 0u, 1u, k20, k21);
            tf2x32(kn0, kn1, 0u, 2u, k30, k31);

            const float MAXA = (float)(20.0 * 3.14159265358979323846 / 180.0);
            float angle  = juniform(k10, k11, 0ull, -MAXA, MAXA);
            float bright = juniform(k30, k31, 0ull, -0.3f, 0.3f);

            const float* bx = boxes + ((size_t)b * Nbox + n) * 4;
            float ymin = bx[0], xmin = bx[1], ymax = bx[2], xmax = bx[3];
            float h  = ymax - ymin;
            float ww = xmax - xmin;
            float longer = fmaxf(h, ww);
            float ps   = floorf(longer * scale);
            float diag = fminf(sqrtf(2.0f) * ps, (float)Wim);
            float oy = ymin + h * 0.5f;
            float ox = xmin + ww * 0.5f;
            float y0 = fmaxf(oy - diag * 0.5f, 0.0f);
            float x0 = fmaxf(ox - diag * 0.5f, 0.0f);
            y0 = (y0 + diag > (float)Him) ? ((float)Him - diag) : y0;
            x0 = (x0 + diag > (float)Wim) ? ((float)Wim - diag) : x0;
            float phi   = fmaxf(floorf(ps), 1.0f);
            float diagi = floorf(diag);

            Geo gg;
            gg.y0i = floorf(y0); gg.x0i = floorf(x0);
            gg.diagi = diagi; gg.phi = phi;
            gg.cc  = (diagi - 1.0f) * 0.5f;
            gg.top = floorf((diagi - phi) * 0.5f);
            gg.r   = 300.0f / phi;
            gg.ca  = cosf(angle);
            gg.sa  = sinf(angle);
            gg.bright = bright;
            gg.k2a = k20; gg.k2b = k21;
            gg.valid = (phi * phi > 60.0f) ? 1 : 0;
            gg.pad = 0;
            g_geo[b][n] = gg;
            sgeo[n] = gg;
        }
        __syncthreads();
        if (n < Nbox) {
            const Geo& N = sgeo[n];
            unsigned m = 0;
            for (int j = n + 1; j < Nbox; j++) {
                const Geo& J = sgeo[j];
                if (J.valid &&
                    N.y0i < J.y0i + J.diagi && N.y0i + N.diagi > J.y0i &&
                    N.x0i < J.x0i + J.diagi && N.x0i + N.diagi > J.x0i)
                    m |= 1u << j;
            }
            g_later[b][n] = m;
        }
        return;
    }

    float acc = 0.0f;
    if (g < NIMG_CHUNK) {
        size_t base = (size_t)b * IMG + (size_t)g * (IMG / NIMG_CHUNK);
        const float4* src  = (const float4*)(images + base);
        float4* dimg = (float4*)(oimg + base);
        float4* dmsk = (float4*)(omask + base);
        const int nvec = (int)((IMG / NIMG_CHUNK) / 4);   // 2400 float4s
        const float4 z = make_float4(0.f, 0.f, 0.f, 0.f);
        float a0 = 0.f, a1 = 0.f, a2 = 0.f, a3 = 0.f;
        int i = threadIdx.x;
        // 8-deep load MLP: one full 2048-wide pass + tail
        if (i + 1792 < nvec) {
            float4 v0 = __ldcs(src + i);
            float4 v1 = __ldcs(src + i + 256);
            float4 v2 = __ldcs(src + i + 512);
            float4 v3 = __ldcs(src + i + 768);
            float4 v4 = __ldcs(src + i + 1024);
            float4 v5 = __ldcs(src + i + 1280);
            float4 v6 = __ldcs(src + i + 1536);
            float4 v7 = __ldcs(src + i + 1792);
            __stcs(dimg + i,        v0); __stcs(dimg + i + 256,  v1);
            __stcs(dimg + i + 512,  v2); __stcs(dimg + i + 768,  v3);
            __stcs(dimg + i + 1024, v4); __stcs(dimg + i + 1280, v5);
            __stcs(dimg + i + 1536, v6); __stcs(dimg + i + 1792, v7);
            __stcs(dmsk + i,        z);  __stcs(dmsk + i + 256,  z);
            __stcs(dmsk + i + 512,  z);  __stcs(dmsk + i + 768,  z);
            __stcs(dmsk + i + 1024, z);  __stcs(dmsk + i + 1280, z);
            __stcs(dmsk + i + 1536, z);  __stcs(dmsk + i + 1792, z);
            a0 += (v0.x + v0.y) + (v0.z + v0.w);
            a1 += (v1.x + v1.y) + (v1.z + v1.w);
            a2 += (v2.x + v2.y) + (v2.z + v2.w);
            a3 += (v3.x + v3.y) + (v3.z + v3.w);
            a0 += (v4.x + v4.y) + (v4.z + v4.w);
            a1 += (v5.x + v5.y) + (v5.z + v5.w);
            a2 += (v6.x + v6.y) + (v6.z + v6.w);
            a3 += (v7.x + v7.y) + (v7.z + v7.w);
            i += 2048;
        }
        for (; i < nvec; i += 256) {
            float4 v = __ldcs(src + i);
            __stcs(dimg + i, v);
            __stcs(dmsk + i, z);
            a0 += (v.x + v.y) + (v.z + v.w);
        }
        acc = (a0 + a1) + (a2 + a3);
    } else {
        float w[3], bb[3];
        wb_for(b, w, bb);
        int gp = g - NIMG_CHUNK;
        int chunk = PTOT / NPAT_CHUNK;                    // 33750
        int base = gp * chunk;
        float a0 = 0.f, a1 = 0.f;
        int i = base + threadIdx.x;
        int end = base + chunk;
        for (; i + 256 < end; i += 512) {
            int c0 = i % 3;
            int c1 = (i + 256) % 3;
            a0 += fminf(fmaxf(w[c0] * patch[i] + bb[c0], -1.0f), 1.0f);
            a1 += fminf(fmaxf(w[c1] * patch[i + 256] + bb[c1], -1.0f), 1.0f);
        }
        if (i < end) {
            int c = i % 3;
            a0 += fminf(fmaxf(w[c] * patch[i] + bb[c], -1.0f), 1.0f);
        }
        acc = a0 + a1;
    }
    __shared__ float sh[256];
    sh[threadIdx.x] = acc;
    __syncthreads();
    for (int s = 128; s > 0; s >>= 1) {
        if (threadIdx.x < s) sh[threadIdx.x] += sh[threadIdx.x + s];
        __syncthreads();
    }
    if (threadIdx.x == 0) {
        if (g < NIMG_CHUNK) g_isum[b][g] = sh[0];
        else                g_psum[b][g - NIMG_CHUNK] = sh[0];
    }
}

// ---------------------------------------------------------------------------
// K2 (k_s): finalize per-image brightness shift. grid (16), 32 thr.
// ---------------------------------------------------------------------------
__global__ void k_s() {
    int b = blockIdx.x;
    int l = threadIdx.x;
    float si = g_isum[b][l] + g_isum[b][l + 32]
             + g_isum[b][l + 64] + g_isum[b][l + 96];
    float sp = (l < NPAT_CHUNK) ? g_psum[b][l] : 0.0f;
    #pragma unroll
    for (int o = 16; o > 0; o >>= 1) {
        si += __shfl_down_sync(0xffffffffu, si, o);
        sp += __shfl_down_sync(0xffffffffu, sp, o);
    }
    if (l == 0) g_s[b] = si / 1228800.0f - sp / 270000.0f;
}

// ---------------------------------------------------------------------------
// K3 (k_heavy): warp-per-row over each box's diag square. For row u the
// valid-src v-range is an interval (py/px linear in v); lanes cover only a
// conservative superset of it, with the EXACT per-pixel test preserved.
// grid (32, 256), block 128 (4 warps).
// ---------------------------------------------------------------------------
__global__ void k_heavy(const float* __restrict__ images,
                        const float* __restrict__ patch,
                        float* __restrict__ oimg,
                        float* __restrict__ omask) {
    int bz = blockIdx.y;
    int b = bz >> 4, n = bz & 15;

    const Geo G = g_geo[b][n];          // uniform broadcast loads
    if (!G.valid) return;
    int diag = (int)G.diagi;
    int warp = threadIdx.x >> 5;
    int lane = threadIdx.x & 31;

    // hoisted per-image scalars
    float s  = g_s[b];
    float w0 = g_w[b][0],  w1 = g_w[b][1],  w2 = g_w[b][2];
    float b0 = g_bj[b][0], b1 = g_bj[b][1], b2 = g_bj[b][2];
    unsigned later = g_later[b][n];
    float lim = G.phi - 1.0f;

    for (int u = blockIdx.x * 4 + warp; u < diag; u += 128) {
        float uf = (float)u;
        // py(v) = P0 - sa*v ; px(v) = Q0 + ca*v   (rearranged ONLY for bounds)
        float P0 = G.cc + G.ca * (uf - G.cc) + G.sa * G.cc - G.top;
        float Q0 = G.cc + G.sa * (uf - G.cc) - G.ca * G.cc - G.top;
        // px constraint (ca >= cos20 > 0)
        float lo = (0.0f - Q0) / G.ca;
        float hi = (lim  - Q0) / G.ca;
        // py constraint
        if (G.sa > 1e-8f) {
            lo = fmaxf(lo, (P0 - lim) / G.sa);
            hi = fminf(hi, P0 / G.sa);
        } else if (G.sa < -1e-8f) {
            lo = fmaxf(lo, P0 / G.sa);
            hi = fminf(hi, (P0 - lim) / G.sa);
        }
        int v0 = max(0, (int)floorf(lo) - 2);
        int v1 = min(diag - 1, (int)ceilf(hi) + 2);

        for (int v = v0 + lane; v <= v1; v += 32) {
            float vf = (float)v;
            // EXACT valid_src test (identical expression to prior rounds)
            float um = uf - G.cc, vm = vf - G.cc;
            float py = G.cc + G.ca * um - G.sa * vm - G.top;
            float px = G.cc + G.sa * um + G.ca * vm - G.top;
            if (!(py >= 0.0f && py <= lim && px >= 0.0f && px <= lim)) continue;

            // skip if any LATER box also writes this pixel
            {
                float yab = G.y0i + uf, xab = G.x0i + vf;
                unsigned mm = later;
                bool taken = false;
                while (mm) {
                    int j = __ffs(mm) - 1;
                    mm &= mm - 1;
                    const Geo J = g_geo[b][j];
                    float uj = yab - J.y0i, vj = xab - J.x0i;
                    if (uj >= 0.f && vj >= 0.f && uj < J.diagi && vj < J.diagi) {
                        float umj = uj - J.cc, vmj = vj - J.cc;
                        float pyj = J.cc + J.ca * umj - J.sa * vmj - J.top;
                        float pxj = J.cc + J.sa * umj + J.ca * vmj - J.top;
                        float lj = J.phi - 1.0f;
                        if (pyj >= 0.f && pyj <= lj && pxj >= 0.f && pxj <= lj) {
                            taken = true; break;
                        }
                    }
                }
                if (taken) continue;
            }

            // final writer: bilinear sample + jitter + noise
            int y = (int)G.y0i + u;
            int x = (int)G.x0i + v;

            float sy = (py + 0.5f) * G.r - 0.5f;
            float sx = (px + 0.5f) * G.r - 0.5f;
            float fy = floorf(sy), fx = floorf(sx);
            float wy = sy - fy, wx = sx - fx;
            int y0c = min(max((int)fy, 0), PHp - 1);
            int y1c = min(y0c + 1, PHp - 1);
            int x0c = min(max((int)fx, 0), PWp - 1);
            int x1c = min(x0c + 1, PWp - 1);
            int o00 = (y0c * PWp + x0c) * 3;
            int o01 = (y0c * PWp + x1c) * 3;
            int o10 = (y1c * PWp + x0c) * 3;
            int o11 = (y1c * PWp + x1c) * 3;

            uint32_t nb = ((uint32_t)y * (uint32_t)Wim + (uint32_t)x) * 3u;
            uint32_t bits[3];
            tf3(G.k2a, G.k2b, nb, bits);

            float omy = 1.0f - wy, omx = 1.0f - wx;
            float w00 = omy * omx, w01 = omy * wx, w10 = wy * omx, w11 = wy * wx;
            size_t base = (((size_t)b * Him + y) * Wim + x) * 3;
            float res[3];
            #pragma unroll
            for (int c = 0; c < 3; c++) {
                float wc = (c == 0) ? w0 : ((c == 1) ? w1 : w2);
                float bc = (c == 0) ? b0 : ((c == 1) ? b1 : b2);
#define ADJ(pp) fminf(fmaxf(fminf(fmaxf(fmaf(wc, (pp), bc), -1.f), 1.f) + s, -1.f), 1.f)
                float samp = ADJ(patch[o00 + c]) * w00 + ADJ(patch[o01 + c]) * w01
                           + ADJ(patch[o10 + c]) * w10 + ADJ(patch[o11 + c]) * w11;
#undef ADJ
                float noise = fmaxf(-0.1f, fmaf(bits_to_unit(bits[c]), 0.2f, -0.1f));
                res[c] = fminf(fmaxf(samp + noise + G.bright, -1.0f), 1.0f);
            }

            float i0 = images[base], i1 = images[base + 1], i2 = images[base + 2];
            oimg[base]      = res[0]; oimg[base + 1]  = res[1]; oimg[base + 2]  = res[2];
            omask[base]     = i0 - res[0];
            omask[base + 1] = i1 - res[1];
            omask[base + 2] = i2 - res[2];
        }
    }
}

// ---------------------------------------------------------------------------
extern "C" void kernel_launch(void* const* d_in, const int* in_sizes, int n_in,
                              void* d_out, int out_size) {
    const float* boxes  = (const float*)d_in[0];
    const float* images = (const float*)d_in[1];
    const float* patch  = (const float*)d_in[2];
    const float* scale  = (const float*)d_in[3];
    float* out   = (float*)d_out;
    float* omask = out + (size_t)Bimg * IMG;

    k_prep<<<dim3(NIMG_CHUNK + NPAT_CHUNK + 1, 16), 256>>>(
        images, patch, boxes, scale, out, omask);
    k_s<<<16, 32>>>();
    k_heavy<<<dim3(32, Bimg * Nbox), 128>>>(images, patch, out, omask);

    (void)in_sizes; (void)n_in; (void)out_size;
}